// round 9
// baseline (speedup 1.0000x reference)
#include <cuda_runtime.h>
#include <math.h>

typedef unsigned long long ull;

#define NB  128      // CTAs (persistent)
#define NT  256      // threads per CTA
#define TSTEPS 128
#define B   128
#define H   1024

// ------------------------- device state (no allocs allowed) -------------------------
__device__ float g_Ht[3 * B * H];
__device__ float g_C [3 * B * H];
__device__ float g_Z [2 * B];
__device__ float g_preP [4][B * 4096];   // k-split partials, layers 0/1
__device__ float g_pre2P[4][B * 4096];   // k-split partials, layer 2
__device__ float g_outP [16][B * H];     // k-split partials, output mix
__device__ float g_gate[3 * B];          // (b, l) row-major == gate.reshape(-1)
__device__ float g_zw[6][H];             // packed z-columns: hh0,bh0,th0,hh1,bh1,th1
__device__ unsigned          g_count;
__device__ volatile unsigned g_release;

// ------------------------- packed f32x2 helpers -------------------------
__device__ __forceinline__ ull pk2(float x, float y) {
    ull r; asm("mov.b64 %0, {%1, %2};" : "=l"(r) : "f"(x), "f"(y)); return r;
}
__device__ __forceinline__ void upk2(ull v, float& x, float& y) {
    asm("mov.b64 {%0, %1}, %2;" : "=f"(x), "=f"(y) : "l"(v));
}
__device__ __forceinline__ ull fma2(ull a, ull b, ull c) {
    ull d; asm("fma.rn.f32x2 %0, %1, %2, %3;" : "=l"(d) : "l"(a), "l"(b), "l"(c)); return d;
}
__device__ __forceinline__ float sigf(float x) { return 1.0f / (1.0f + expf(-x)); }

// ------------------------- grid barrier (all 128 CTAs resident) -------------------------
__device__ __forceinline__ void gsync(unsigned& epoch) {
    __syncthreads();
    if (threadIdx.x == 0) {
        epoch++;
        __threadfence();                           // release
        unsigned prev = atomicAdd(&g_count, 1u);
        if (prev == epoch * (unsigned)gridDim.x - 1u) {
            g_release = epoch;
        } else {
            while (g_release < epoch) __nanosleep(100);
        }
        __threadfence();                           // acquire
    }
    __syncthreads();
}

// ------------------------- segmented GEMM phase -------------------------
// out[r, n0+n] (+)= sum over chunks [c0,c1) of sc_s[r] * A_s[r,k] * W_s[k, n0+n]
// chunk c: segment = c>>5, k-offset within segment = (c&31)*32.
// BM=128 (all rows), BN=128 columns at n0, BK=32. 256 threads, 8x8 tile,
// accumulators packed along M (f32x2 row pairs).
__device__ void seg_gemm(const float* A0, const float* sc0,
                         const float* A1, const float* sc1,
                         const float* A2, const float* sc2,
                         const float* W0, const float* W1, const float* W2,
                         int ldw, int n0, int c0, int c1,
                         float* outp, int ldo,
                         float (*As)[130], float (*Bs)[128])
{
    const int tid = threadIdx.x;
    const int tr8 = (tid >> 4) << 3;     // 8 output rows tr8..tr8+7
    const int tc8 = (tid & 15) << 3;     // 8 output cols (local) tc8..tc8+7

    ull acc[4][8];
#pragma unroll
    for (int p = 0; p < 4; p++)
#pragma unroll
        for (int c = 0; c < 8; c++) acc[p][c] = 0ull;

    float4 aR[4];
    float  bR[16];

    auto load_chunk = [&](int c) {
        const int seg = c >> 5;
        const int kl  = (c & 31) << 5;
        const float* A  = (seg == 0) ? A0 : ((seg == 1) ? A1 : A2);
        const float* sc = (seg == 0) ? sc0 : ((seg == 1) ? sc1 : sc2);
        const float* W  = (seg == 0) ? W0 : ((seg == 1) ? W1 : W2);
#pragma unroll
        for (int p = 0; p < 4; p++) {
            int f = tid + (p << 8);
            int row = f >> 3, c4 = f & 7;
            float4 v = *reinterpret_cast<const float4*>(A + row * 1024 + kl + (c4 << 2));
            if (sc) { float s = sc[row]; v.x *= s; v.y *= s; v.z *= s; v.w *= s; }
            aR[p] = v;
        }
#pragma unroll
        for (int p = 0; p < 16; p++) {
            int f = tid + (p << 8);
            int n = f & 127, kk = f >> 7;
            bR[p] = W[(kl + kk) * ldw + n0 + n];
        }
    };
    auto store_chunk = [&]() {
#pragma unroll
        for (int p = 0; p < 4; p++) {
            int f = tid + (p << 8);
            int row = f >> 3, k = (f & 7) << 2;
            As[k + 0][row] = aR[p].x;
            As[k + 1][row] = aR[p].y;
            As[k + 2][row] = aR[p].z;
            As[k + 3][row] = aR[p].w;
        }
#pragma unroll
        for (int p = 0; p < 16; p++) {
            int f = tid + (p << 8);
            Bs[f >> 7][f & 127] = bR[p];
        }
    };
    auto compute_chunk = [&]() {
#pragma unroll 8
        for (int k = 0; k < 32; k++) {
            ull a0 = *reinterpret_cast<const ull*>(&As[k][tr8 + 0]);
            ull a1 = *reinterpret_cast<const ull*>(&As[k][tr8 + 2]);
            ull a2 = *reinterpret_cast<const ull*>(&As[k][tr8 + 4]);
            ull a3 = *reinterpret_cast<const ull*>(&As[k][tr8 + 6]);
            float4 bv0 = *reinterpret_cast<const float4*>(&Bs[k][tc8 + 0]);
            float4 bv1 = *reinterpret_cast<const float4*>(&Bs[k][tc8 + 4]);
            ull bb[8];
            bb[0] = pk2(bv0.x, bv0.x); bb[1] = pk2(bv0.y, bv0.y);
            bb[2] = pk2(bv0.z, bv0.z); bb[3] = pk2(bv0.w, bv0.w);
            bb[4] = pk2(bv1.x, bv1.x); bb[5] = pk2(bv1.y, bv1.y);
            bb[6] = pk2(bv1.z, bv1.z); bb[7] = pk2(bv1.w, bv1.w);
#pragma unroll
            for (int c = 0; c < 8; c++) {
                acc[0][c] = fma2(a0, bb[c], acc[0][c]);
                acc[1][c] = fma2(a1, bb[c], acc[1][c]);
                acc[2][c] = fma2(a2, bb[c], acc[2][c]);
                acc[3][c] = fma2(a3, bb[c], acc[3][c]);
            }
        }
    };

    load_chunk(c0);
    store_chunk();
    __syncthreads();
    for (int c = c0 + 1; c < c1; c++) {
        load_chunk(c);           // LDGs overlap with compute below
        compute_chunk();
        __syncthreads();
        store_chunk();
        __syncthreads();
    }
    compute_chunk();

#pragma unroll
    for (int p = 0; p < 4; p++) {
        int r0 = tr8 + 2 * p;
#pragma unroll
        for (int c = 0; c < 8; c++) {
            float v0, v1; upk2(acc[p][c], v0, v1);
            int col = n0 + tc8 + c;
            outp[r0 * ldo + col] = v0;
            outp[(r0 + 1) * ldo + col] = v1;
        }
    }
    __syncthreads();   // smem safe for next phase user
}

// ------------------------- 3-way block reduction -------------------------
__device__ __forceinline__ void red3(float* red, float s0, float s1, float s2,
                                     float& r0, float& r1, float& r2)
{
    int tid = threadIdx.x;
    red[tid] = s0; red[256 + tid] = s1; red[512 + tid] = s2;
    __syncthreads();
    for (int off = 128; off > 0; off >>= 1) {
        if (tid < off) {
            red[tid]       += red[tid + off];
            red[256 + tid] += red[256 + tid + off];
            red[512 + tid] += red[512 + tid + off];
        }
        __syncthreads();
    }
    r0 = red[0]; r1 = red[256]; r2 = red[512];
    __syncthreads();
}

// ------------------------- HMLSTM cell (one CTA = one batch row) -------------------------
__device__ void cell_hm(int b, int l, int t,
                        const float* xb, const float* xtop,
                        const float* zw_hh, const float* zw_bh, const float* zw_th,
                        float bz, const float* bias,
                        const float (*preP)[B * 4096],
                        const int* length, float z_lm1, float* red)
{
    const int tid = threadIdx.x;
    float* hrow = g_Ht + (l * B + b) * H;
    float* crow = g_C  + (l * B + b) * H;
    const float z_tm1 = g_Z[l * B + b];

    float s0 = 0.f, s1 = 0.f, s2 = 0.f;
    for (int k = tid; k < H; k += NT) {
        s0 += hrow[k] * zw_hh[k];
        s1 += xb[k]   * zw_bh[k];
        s2 += xtop[k] * zw_th[k];
    }
    float d0, d1, d2;
    red3(red, s0, s1, s2, d0, d1, d2);
    if (tid == 0) {
        float prez = d0 + bz + z_lm1 * d1 + z_tm1 * d2;
        // round-half-even(clip((z+1)/2,0,1)) == (z > 0)
        g_Z[l * B + b] = (prez > 0.0f) ? 1.0f : 0.0f;
    }

    const float tm   = (t < length[b]) ? 1.0f : 0.0f;
    const float keep = 1.0f - z_tm1;
    const float cp   = (1.0f - z_tm1) * (1.0f - z_lm1);
    const float* P0 = preP[0] + b * 4096;
    const float* P1 = preP[1] + b * 4096;
    const float* P2 = preP[2] + b * 4096;
    const float* P3 = preP[3] + b * 4096;

    for (int h = tid; h < H; h += NT) {
        float f = P0[h]        + P1[h]        + P2[h]        + P3[h]        + bias[h];
        float i = P0[1024 + h] + P1[1024 + h] + P2[1024 + h] + P3[1024 + h] + bias[1024 + h];
        float o = P0[2048 + h] + P1[2048 + h] + P2[2048 + h] + P3[2048 + h] + bias[2048 + h];
        float g = P0[3072 + h] + P1[3072 + h] + P2[3072 + h] + P3[3072 + h] + bias[3072 + h];
        float c_old = crow[h], h_old = hrow[h];
        float c1 = keep * sigf(f) * c_old + sigf(i) * tanhf(g);
        float h1 = sigf(o) * tanhf(c1);
        float hn = cp * h_old + (1.0f - cp) * h1;
        float cn = cp * c_old + (1.0f - cp) * c1;
        hrow[h] = tm * hn + (1.0f - tm) * h_old;
        crow[h] = tm * cn + (1.0f - tm) * c_old;
    }
}

// plain LSTM (layer 2) commit
__device__ void cell_l2(int b, int t, const float* bias, const int* length)
{
    const int tid = threadIdx.x;
    float* hrow = g_Ht + (2 * B + b) * H;
    float* crow = g_C  + (2 * B + b) * H;
    const float cp = 1.0f - g_Z[b];     // z_tm1=0, z_lm1=Z0(new)
    const float tm = (t < length[b]) ? 1.0f : 0.0f;
    const float* P0 = g_pre2P[0] + b * 4096;
    const float* P1 = g_pre2P[1] + b * 4096;
    const float* P2 = g_pre2P[2] + b * 4096;
    const float* P3 = g_pre2P[3] + b * 4096;

    for (int h = tid; h < H; h += NT) {
        float f = P0[h]        + P1[h]        + P2[h]        + P3[h]        + bias[h];
        float i = P0[1024 + h] + P1[1024 + h] + P2[1024 + h] + P3[1024 + h] + bias[1024 + h];
        float o = P0[2048 + h] + P1[2048 + h] + P2[2048 + h] + P3[2048 + h] + bias[2048 + h];
        float g = P0[3072 + h] + P1[3072 + h] + P2[3072 + h] + P3[3072 + h] + bias[3072 + h];
        float c_old = crow[h], h_old = hrow[h];
        float c1 = sigf(f) * c_old + sigf(i) * tanhf(g);
        float h1 = sigf(o) * tanhf(c1);
        float hn = cp * h_old + (1.0f - cp) * h1;
        float cn = cp * c_old + (1.0f - cp) * c1;
        hrow[h] = tm * hn + (1.0f - tm) * h_old;
        crow[h] = tm * cn + (1.0f - tm) * c_old;
    }
}

// gate[b][l] = sigmoid( Ht.reshape(B,3H)[b] . Wgate[:,l] + bgate[l] )
__device__ void gate_row(int b, const float* Wgate, const float* bgate, float* red)
{
    const int tid = threadIdx.x;
    float s0 = 0.f, s1 = 0.f, s2 = 0.f;
    const float* hb = g_Ht + b * 3072;   // flat view == reshape(B, L*H) row b
    for (int j = tid; j < 3072; j += NT) {
        float h = hb[j];
        s0 += h * Wgate[j * 3 + 0];
        s1 += h * Wgate[j * 3 + 1];
        s2 += h * Wgate[j * 3 + 2];
    }
    float d0, d1, d2;
    red3(red, s0, s1, s2, d0, d1, d2);
    if (tid == 0) {
        g_gate[b * 3 + 0] = sigf(d0 + bgate[0]);
        g_gate[b * 3 + 1] = sigf(d1 + bgate[1]);
        g_gate[b * 3 + 2] = sigf(d2 + bgate[2]);
    }
}

// out[t,b,:] = sum_16 parts + (sum_l gate_flat[l*128+b]) * bout
__device__ void finalize_row(int b, int t, const float* bout, float* out)
{
    const int tid = threadIdx.x;
    const float gs = g_gate[b] + g_gate[128 + b] + g_gate[256 + b];  // flat indices!
    float* o = out + ((size_t)t * B + b) * H;
    for (int h = tid; h < H; h += NT) {
        float s = gs * bout[h];
#pragma unroll
        for (int p = 0; p < 16; p++) s += g_outP[p][b * H + h];
        o[h] = s;
    }
}

// ------------------------- init kernel -------------------------
__global__ void __launch_bounds__(256)
init_kernel(const float* Whh0, const float* Wbh0, const float* Wth0,
            const float* Whh1, const float* Wbh1, const float* Wth1)
{
    int idx = blockIdx.x * blockDim.x + threadIdx.x;
    for (int i = idx; i < 3 * B * H; i += gridDim.x * blockDim.x) {
        g_Ht[i] = 0.f; g_C[i] = 0.f;
    }
    if (idx < 2 * B) g_Z[idx] = 0.f;
    if (idx < H) {
        g_zw[0][idx] = Whh0[idx * 4097 + 4096];
        g_zw[1][idx] = Wbh0[idx * 4097 + 4096];
        g_zw[2][idx] = Wth0[idx * 4097 + 4096];
        g_zw[3][idx] = Whh1[idx * 4097 + 4096];
        g_zw[4][idx] = Wbh1[idx * 4097 + 4096];
        g_zw[5][idx] = Wth1[idx * 4097 + 4096];
    }
    if (idx == 0) { g_count = 0; g_release = 0; }
}

// ------------------------- persistent kernel -------------------------
__global__ void __launch_bounds__(256, 1)
hm_persist(const float* __restrict__ input_, const int* __restrict__ length,
           const float* __restrict__ Wbh0, const float* __restrict__ Whh0,
           const float* __restrict__ Wth0, const float* __restrict__ b0,
           const float* __restrict__ Wbh1, const float* __restrict__ Whh1,
           const float* __restrict__ Wth1, const float* __restrict__ b1,
           const float* __restrict__ Wih2, const float* __restrict__ Whh2,
           const float* __restrict__ b2,   const float* __restrict__ Wout,
           const float* __restrict__ bout, const float* __restrict__ Wgate,
           const float* __restrict__ bgate, float* __restrict__ out)
{
    __shared__ float As[32][130];
    __shared__ float Bs[32][128];
    __shared__ float red[3 * 256];

    const int bx = blockIdx.x;
    unsigned epoch = 0;

    const int ntB = bx >> 2, ksB = bx & 3;    // N=4096 GEMMs: 32 n-tiles x 4 k-splits
    const int ntO = bx >> 4, ksO = bx & 15;   // N=1024 out-mix: 8 n-tiles x 16 k-splits

    const float* Ht0 = g_Ht;
    const float* Ht1 = g_Ht + B * H;
    const float* Ht2 = g_Ht + 2 * B * H;

    const float bz0 = b0[4096];
    const float bz1 = b1[4096];

    for (int t = 0; t < TSTEPS; t++) {
        const float* xt = input_ + (size_t)t * B * H;

        // P1: GEMM layer0 (+ commit layer2 of t-1, finalize output of t-1)
        seg_gemm(Ht0, nullptr, xt, nullptr, Ht1, g_Z,
                 Whh0, Wbh0, Wth0, 4097, ntB * 128, ksB * 24, ksB * 24 + 24,
                 g_preP[ksB], 4096, As, Bs);
        if (t > 0) {
            cell_l2(bx, t - 1, b2, length);
            __syncthreads();
            finalize_row(bx, t - 1, bout, out);
        }
        gsync(epoch);

        // P2: cell layer0 (z_lm1 = 1)
        cell_hm(bx, 0, t, xt + bx * H, Ht1 + bx * H,
                g_zw[0], g_zw[1], g_zw[2], bz0, b0, g_preP, length, 1.0f, red);
        gsync(epoch);

        // P3: GEMM layer1 (scales: Z0 new for bottom, Z1 old for top)
        seg_gemm(Ht1, nullptr, Ht0, g_Z, Ht2, g_Z + B,
                 Whh1, Wbh1, Wth1, 4097, ntB * 128, ksB * 24, ksB * 24 + 24,
                 g_preP[ksB], 4096, As, Bs);
        gsync(epoch);

        // P4: cell layer1 (z_lm1 = Z0 new)
        cell_hm(bx, 1, t, Ht0 + bx * H, Ht2 + bx * H,
                g_zw[3], g_zw[4], g_zw[5], bz1, b1, g_preP, length, g_Z[bx], red);
        gsync(epoch);

        // P5: GEMM layer2 (2 segments) + gate mixing
        seg_gemm(Ht2, nullptr, Ht1, nullptr, nullptr, nullptr,
                 Whh2, Wih2, nullptr, 4096, ntB * 128, ksB * 16, ksB * 16 + 16,
                 g_pre2P[ksB], 4096, As, Bs);
        gate_row(bx, Wgate, bgate, red);
        gsync(epoch);

        // P6: gated output mix (reads new Ht0/Ht1, OLD Ht2)
        seg_gemm(Ht0, g_gate + 0, Ht1, g_gate + 128, Ht2, g_gate + 256,
                 Wout, Wout, Wout, 1024, ntO * 128, ksO * 6, ksO * 6 + 6,
                 g_outP[ksO], 1024, As, Bs);
        gsync(epoch);
    }

    // epilogue: commit last layer2 state + final output
    cell_l2(bx, TSTEPS - 1, b2, length);
    __syncthreads();
    finalize_row(bx, TSTEPS - 1, bout, out);
}

// ------------------------- host -------------------------
extern "C" void kernel_launch(void* const* d_in, const int* in_sizes, int n_in,
                              void* d_out, int out_size)
{
    const float* input_ = (const float*)d_in[0];
    const int*   length = (const int*)d_in[1];
    const float* Wbh0 = (const float*)d_in[2];
    const float* Whh0 = (const float*)d_in[3];
    const float* Wth0 = (const float*)d_in[4];
    const float* b0   = (const float*)d_in[5];
    const float* Wbh1 = (const float*)d_in[6];
    const float* Whh1 = (const float*)d_in[7];
    const float* Wth1 = (const float*)d_in[8];
    const float* b1   = (const float*)d_in[9];
    const float* Wih2 = (const float*)d_in[10];
    const float* Whh2 = (const float*)d_in[11];
    const float* b2   = (const float*)d_in[12];
    const float* Wout = (const float*)d_in[13];
    const float* bout = (const float*)d_in[14];
    const float* Wgate = (const float*)d_in[15];
    const float* bgate = (const float*)d_in[16];
    float* out = (float*)d_out;

    init_kernel<<<128, 256>>>(Whh0, Wbh0, Wth0, Whh1, Wbh1, Wth1);
    hm_persist<<<NB, NT>>>(input_, length, Wbh0, Whh0, Wth0, b0,
                           Wbh1, Whh1, Wth1, b1, Wih2, Whh2, b2,
                           Wout, bout, Wgate, bgate, out);
}

// round 10
// speedup vs baseline: 1.0296x; 1.0296x over previous
#include <cuda_runtime.h>
#include <math.h>

typedef unsigned long long ull;

#define NB  128      // persistent CTAs
#define NT  512      // threads per CTA
#define TSTEPS 128
#define B   128
#define H   1024

#define AS2_PAD    260                    // floats per k-row of duplicated A
#define AS2_FLOATS (32 * AS2_PAD)         // 8320
#define BS_FLOATS  (32 * 256)             // one stage
#define SMEM_FLOATS (AS2_FLOATS + 2 * BS_FLOATS + 3 * NT)

// ------------------------- device state (no allocs allowed) -------------------------
__device__ float g_Ht[3 * B * H];
__device__ float g_C [3 * B * H];
__device__ float g_Z [2 * B];
__device__ float g_preP [8][B * 4096];   // k-split partials, layers 0/1
__device__ float g_pre2P[8][B * 4096];   // k-split partials, layer 2
__device__ float g_outP [32][B * H];     // k-split partials, output mix
__device__ float g_gate[3 * B];          // flat == gate.reshape(-1) (b-major, l inner)
__device__ float g_zw[6][H];             // z-columns: hh0,bh0,th0,hh1,bh1,th1
__device__ float g_W6[6][1024 * 4096];   // repacked weights (z-col dropped, ldw=4096)
__device__ unsigned          g_count;
__device__ volatile unsigned g_release;

// ------------------------- helpers -------------------------
__device__ __forceinline__ ull pk2(float x, float y) {
    ull r; asm("mov.b64 %0, {%1, %2};" : "=l"(r) : "f"(x), "f"(y)); return r;
}
__device__ __forceinline__ void upk2(ull v, float& x, float& y) {
    asm("mov.b64 {%0, %1}, %2;" : "=f"(x), "=f"(y) : "l"(v));
}
__device__ __forceinline__ ull fma2(ull a, ull b, ull c) {
    ull d; asm("fma.rn.f32x2 %0, %1, %2, %3;" : "=l"(d) : "l"(a), "l"(b), "l"(c)); return d;
}
__device__ __forceinline__ float sigf(float x) { return 1.0f / (1.0f + expf(-x)); }

__device__ __forceinline__ void cp_async16(float* smem_dst, const float* gsrc) {
    unsigned s = (unsigned)__cvta_generic_to_shared(smem_dst);
    asm volatile("cp.async.cg.shared.global [%0], [%1], 16;" :: "r"(s), "l"(gsrc));
}
#define CP_COMMIT() asm volatile("cp.async.commit_group;" ::: "memory")
#define CP_WAIT0()  asm volatile("cp.async.wait_group 0;" ::: "memory")

// ------------------------- grid barrier (all 128 CTAs resident) -------------------------
__device__ __forceinline__ void gsync(unsigned& epoch) {
    __syncthreads();
    if (threadIdx.x == 0) {
        epoch++;
        __threadfence();
        unsigned prev = atomicAdd(&g_count, 1u);
        if (prev == epoch * (unsigned)gridDim.x - 1u) {
            g_release = epoch;
        } else {
            while (g_release < epoch) __nanosleep(40);
        }
        __threadfence();
    }
    __syncthreads();
}

// ------------------------- segmented GEMM phase -------------------------
// out[r, n] (+)= sum over chunks [c0,c1) of sc_seg[r] * A_seg[r,k] * W_seg[k,n]
// chunk c: seg = c>>5, k within segment = (c&31)*32. BM=128, BN=256, BK=32.
// 512 threads; thread tile 8 rows x (4 + 4) cols; acc packed along N (f32x2).
__device__ void seg_gemm(const float* A0, const float* sc0,
                         const float* A1, const float* sc1,
                         const float* A2, const float* sc2,
                         const float* W0, const float* W1, const float* W2,
                         int ldw, int n0, int c0, int c1,
                         float* outp, int ldo,
                         float* As2, float* Bs0)
{
    const int tid  = threadIdx.x;
    const int tr8  = (tid >> 5) << 3;   // warp id * 8 : 8 output rows (warp-uniform)
    const int tc4  = (tid & 31) << 2;   // cols tc4..+3 and 128+tc4..+3
    const int rowA = tid >> 3;          // A-load rows: rowA, rowA+64
    const int kg   = tid & 7;           // A-load k-group (4 floats)

    ull acc[8][4];
#pragma unroll
    for (int r = 0; r < 8; r++)
#pragma unroll
        for (int c = 0; c < 4; c++) acc[r][c] = 0ull;

    // per-phase row scales (2 rows per thread, 3 segments)
    float sv[3][2];
    sv[0][0] = sc0 ? sc0[rowA] : 1.0f;  sv[0][1] = sc0 ? sc0[rowA + 64] : 1.0f;
    sv[1][0] = sc1 ? sc1[rowA] : 1.0f;  sv[1][1] = sc1 ? sc1[rowA + 64] : 1.0f;
    sv[2][0] = sc2 ? sc2[rowA] : 1.0f;  sv[2][1] = sc2 ? sc2[rowA + 64] : 1.0f;

    float4 aR[2];

    auto issue_chunk = [&](int c, int s) {
        const int seg = c >> 5;
        const int kl  = (c & 31) << 5;
        const float* A = (seg == 0) ? A0 : ((seg == 1) ? A1 : A2);
        const float* W = (seg == 0) ? W0 : ((seg == 1) ? W1 : W2);
        float* bdst = Bs0 + s * BS_FLOATS;
#pragma unroll
        for (int p = 0; p < 4; p++) {
            int idx = tid + (p << 9);
            int kk = idx >> 6, n4 = (idx & 63) << 2;
            cp_async16(bdst + (kk << 8) + n4, W + (size_t)(kl + kk) * ldw + n0 + n4);
        }
        CP_COMMIT();
#pragma unroll
        for (int p = 0; p < 2; p++) {
            int row = rowA + (p << 6);
            float4 v = *reinterpret_cast<const float4*>(A + row * 1024 + kl + (kg << 2));
            float s2 = sv[seg][p];
            v.x *= s2; v.y *= s2; v.z *= s2; v.w *= s2;
            aR[p] = v;
        }
    };
    auto store_A = [&]() {
#pragma unroll
        for (int p = 0; p < 2; p++) {
            int row2 = (rowA + (p << 6)) << 1;
            float4 v = aR[p];
            *reinterpret_cast<ull*>(As2 + (kg * 4 + 0) * AS2_PAD + row2) = pk2(v.x, v.x);
            *reinterpret_cast<ull*>(As2 + (kg * 4 + 1) * AS2_PAD + row2) = pk2(v.y, v.y);
            *reinterpret_cast<ull*>(As2 + (kg * 4 + 2) * AS2_PAD + row2) = pk2(v.z, v.z);
            *reinterpret_cast<ull*>(As2 + (kg * 4 + 3) * AS2_PAD + row2) = pk2(v.w, v.w);
        }
    };
    auto compute = [&](int s) {
        const float* bb = Bs0 + s * BS_FLOATS;
#pragma unroll 4
        for (int k = 0; k < 32; k++) {
            const float* arow = As2 + k * AS2_PAD + (tr8 << 1);
            ulonglong2 a01 = *reinterpret_cast<const ulonglong2*>(arow);
            ulonglong2 a23 = *reinterpret_cast<const ulonglong2*>(arow + 4);
            ulonglong2 a45 = *reinterpret_cast<const ulonglong2*>(arow + 8);
            ulonglong2 a67 = *reinterpret_cast<const ulonglong2*>(arow + 12);
            ulonglong2 b0  = *reinterpret_cast<const ulonglong2*>(bb + (k << 8) + tc4);
            ulonglong2 b1  = *reinterpret_cast<const ulonglong2*>(bb + (k << 8) + 128 + tc4);
            ull ar[8] = {a01.x, a01.y, a23.x, a23.y, a45.x, a45.y, a67.x, a67.y};
#pragma unroll
            for (int r = 0; r < 8; r++) {
                acc[r][0] = fma2(ar[r], b0.x, acc[r][0]);
                acc[r][1] = fma2(ar[r], b0.y, acc[r][1]);
                acc[r][2] = fma2(ar[r], b1.x, acc[r][2]);
                acc[r][3] = fma2(ar[r], b1.y, acc[r][3]);
            }
        }
    };

    // prologue
    issue_chunk(c0, 0);
    store_A();
    CP_WAIT0();
    __syncthreads();

    int s = 0;
    for (int c = c0; c < c1; c++) {
        bool more = (c + 1 < c1);
        if (more) issue_chunk(c + 1, s ^ 1);
        compute(s);
        __syncthreads();              // everyone done reading As2
        if (more) store_A();
        CP_WAIT0();
        __syncthreads();
        s ^= 1;
    }

    // epilogue: acc[r][0..1] -> cols n0+tc4..+3 ; acc[r][2..3] -> n0+128+tc4..+3
#pragma unroll
    for (int r = 0; r < 8; r++) {
        float* o = outp + (size_t)(tr8 + r) * ldo + n0;
        *reinterpret_cast<ulonglong2*>(o + tc4)       = make_ulonglong2(acc[r][0], acc[r][1]);
        *reinterpret_cast<ulonglong2*>(o + 128 + tc4) = make_ulonglong2(acc[r][2], acc[r][3]);
    }
}

// ------------------------- 3-way block reduction (512 thr) -------------------------
__device__ __forceinline__ void red3(float* red, float s0, float s1, float s2,
                                     float& r0, float& r1, float& r2)
{
    int tid = threadIdx.x;
    red[tid] = s0; red[NT + tid] = s1; red[2 * NT + tid] = s2;
    __syncthreads();
    for (int off = NT / 2; off > 0; off >>= 1) {
        if (tid < off) {
            red[tid]          += red[tid + off];
            red[NT + tid]     += red[NT + tid + off];
            red[2 * NT + tid] += red[2 * NT + tid + off];
        }
        __syncthreads();
    }
    r0 = red[0]; r1 = red[NT]; r2 = red[2 * NT];
    __syncthreads();
}

// ------------------------- HMLSTM cell (one CTA = one batch row) -------------------------
__device__ void cell_hm(int b, int l, int t,
                        const float* xb, const float* xtop,
                        const float* zw_hh, const float* zw_bh, const float* zw_th,
                        float bz, const float* bias,
                        const int* length, float z_lm1, float* red)
{
    const int tid = threadIdx.x;
    float* hrow = g_Ht + (l * B + b) * H;
    float* crow = g_C  + (l * B + b) * H;
    const float z_tm1 = g_Z[l * B + b];

    float s0 = 0.f, s1 = 0.f, s2 = 0.f;
    for (int k = tid; k < H; k += NT) {
        s0 += hrow[k] * zw_hh[k];
        s1 += xb[k]   * zw_bh[k];
        s2 += xtop[k] * zw_th[k];
    }
    float d0, d1, d2;
    red3(red, s0, s1, s2, d0, d1, d2);
    if (tid == 0) {
        float prez = d0 + bz + z_lm1 * d1 + z_tm1 * d2;
        // round-half-even(clip((z+1)/2,0,1)) == (z > 0)
        g_Z[l * B + b] = (prez > 0.0f) ? 1.0f : 0.0f;
    }

    const float tm   = (t < length[b]) ? 1.0f : 0.0f;
    const float keep = 1.0f - z_tm1;
    const float cp   = (1.0f - z_tm1) * (1.0f - z_lm1);

    for (int h = tid; h < H; h += NT) {
        float f = bias[h], i = bias[1024 + h], o = bias[2048 + h], g = bias[3072 + h];
#pragma unroll
        for (int p = 0; p < 8; p++) {
            const float* P = g_preP[p] + b * 4096;
            f += P[h]; i += P[1024 + h]; o += P[2048 + h]; g += P[3072 + h];
        }
        float c_old = crow[h], h_old = hrow[h];
        float c1 = keep * sigf(f) * c_old + sigf(i) * tanhf(g);
        float h1 = sigf(o) * tanhf(c1);
        float hn = cp * h_old + (1.0f - cp) * h1;
        float cn = cp * c_old + (1.0f - cp) * c1;
        hrow[h] = tm * hn + (1.0f - tm) * h_old;
        crow[h] = tm * cn + (1.0f - tm) * c_old;
    }
}

// plain LSTM (layer 2) commit
__device__ void cell_l2(int b, int t, const float* bias, const int* length)
{
    const int tid = threadIdx.x;
    float* hrow = g_Ht + (2 * B + b) * H;
    float* crow = g_C  + (2 * B + b) * H;
    const float cp = 1.0f - g_Z[b];     // z_tm1=0, z_lm1=Z0(new)
    const float tm = (t < length[b]) ? 1.0f : 0.0f;

    for (int h = tid; h < H; h += NT) {
        float f = bias[h], i = bias[1024 + h], o = bias[2048 + h], g = bias[3072 + h];
#pragma unroll
        for (int p = 0; p < 8; p++) {
            const float* P = g_pre2P[p] + b * 4096;
            f += P[h]; i += P[1024 + h]; o += P[2048 + h]; g += P[3072 + h];
        }
        float c_old = crow[h], h_old = hrow[h];
        float c1 = sigf(f) * c_old + sigf(i) * tanhf(g);
        float h1 = sigf(o) * tanhf(c1);
        float hn = cp * h_old + (1.0f - cp) * h1;
        float cn = cp * c_old + (1.0f - cp) * c1;
        hrow[h] = tm * hn + (1.0f - tm) * h_old;
        crow[h] = tm * cn + (1.0f - tm) * c_old;
    }
}

// gate[b][l] = sigmoid( Ht.reshape(B,3H)[b] . Wgate[:,l] + bgate[l] )
__device__ void gate_row(int b, const float* Wgate, const float* bgate, float* red)
{
    const int tid = threadIdx.x;
    float s0 = 0.f, s1 = 0.f, s2 = 0.f;
    const float* hb = g_Ht + b * 3072;   // flat view == reshape(B, L*H) row b
    for (int j = tid; j < 3072; j += NT) {
        float h = hb[j];
        s0 += h * Wgate[j * 3 + 0];
        s1 += h * Wgate[j * 3 + 1];
        s2 += h * Wgate[j * 3 + 2];
    }
    float d0, d1, d2;
    red3(red, s0, s1, s2, d0, d1, d2);
    if (tid == 0) {
        g_gate[b * 3 + 0] = sigf(d0 + bgate[0]);
        g_gate[b * 3 + 1] = sigf(d1 + bgate[1]);
        g_gate[b * 3 + 2] = sigf(d2 + bgate[2]);
    }
}

// out[t,b,:] = sum_32 partials + (gate_flat[b]+gate_flat[128+b]+gate_flat[256+b]) * bout
__device__ void finalize_row(int b, int t, const float* bout, float* out)
{
    const int tid = threadIdx.x;
    const float gs = g_gate[b] + g_gate[128 + b] + g_gate[256 + b];
    float* o = out + ((size_t)t * B + b) * H;
    for (int h = tid; h < H; h += NT) {
        float s = gs * bout[h];
#pragma unroll
        for (int p = 0; p < 32; p++) s += g_outP[p][b * H + h];
        o[h] = s;
    }
}

// ------------------------- init kernels -------------------------
__global__ void __launch_bounds__(1024)
repack_kernel(const float* Whh0, const float* Wbh0, const float* Wth0,
              const float* Whh1, const float* Wbh1, const float* Wth1)
{
    const float* srcs[6] = {Whh0, Wbh0, Wth0, Whh1, Wbh1, Wth1};
    int slab = blockIdx.y;
    int idx = blockIdx.x * 1024 + threadIdx.x;     // 0 .. 4194303
    int k = idx >> 12, n = idx & 4095;
    g_W6[slab][idx] = srcs[slab][(size_t)k * 4097 + n];
}

__global__ void __launch_bounds__(512)
init_misc(const float* Whh0, const float* Wbh0, const float* Wth0,
          const float* Whh1, const float* Wbh1, const float* Wth1)
{
    int idx = blockIdx.x * blockDim.x + threadIdx.x;
    for (int i = idx; i < 3 * B * H; i += gridDim.x * blockDim.x) {
        g_Ht[i] = 0.f; g_C[i] = 0.f;
    }
    if (idx < 2 * B) g_Z[idx] = 0.f;
    if (idx < H) {
        g_zw[0][idx] = Whh0[(size_t)idx * 4097 + 4096];
        g_zw[1][idx] = Wbh0[(size_t)idx * 4097 + 4096];
        g_zw[2][idx] = Wth0[(size_t)idx * 4097 + 4096];
        g_zw[3][idx] = Whh1[(size_t)idx * 4097 + 4096];
        g_zw[4][idx] = Wbh1[(size_t)idx * 4097 + 4096];
        g_zw[5][idx] = Wth1[(size_t)idx * 4097 + 4096];
    }
    if (idx == 0) { g_count = 0; g_release = 0; }
}

// ------------------------- persistent kernel -------------------------
__global__ void __launch_bounds__(NT, 1)
hm_persist(const float* __restrict__ input_, const int* __restrict__ length,
           const float* __restrict__ b0,   const float* __restrict__ b1,
           const float* __restrict__ Wih2, const float* __restrict__ Whh2,
           const float* __restrict__ b2,   const float* __restrict__ Wout,
           const float* __restrict__ bout, const float* __restrict__ Wgate,
           const float* __restrict__ bgate, float* __restrict__ out)
{
    extern __shared__ float smem[];
    float* As2 = smem;
    float* Bs0 = smem + AS2_FLOATS;
    float* red = smem + AS2_FLOATS + 2 * BS_FLOATS;

    const int bx = blockIdx.x;
    unsigned epoch = 0;

    const int ntB = bx >> 3, ksB = bx & 7;    // N=4096: 16 n-tiles x 8 k-splits
    const int ntO = bx & 3,  ksO = bx >> 2;   // N=1024: 4 n-tiles x 32 k-splits

    const float* Ht0 = g_Ht;
    const float* Ht1 = g_Ht + B * H;
    const float* Ht2 = g_Ht + 2 * B * H;

    const float bz0 = b0[4096];
    const float bz1 = b1[4096];

    for (int t = 0; t < TSTEPS; t++) {
        const float* xt = input_ + (size_t)t * B * H;

        // P1: GEMM layer0 (+ tail: commit layer2 of t-1, finalize output of t-1)
        seg_gemm(Ht0, nullptr, xt, nullptr, Ht1, g_Z,
                 g_W6[0], g_W6[1], g_W6[2], 4096, ntB * 256, ksB * 12, ksB * 12 + 12,
                 g_preP[ksB], 4096, As2, Bs0);
        if (t > 0) {
            cell_l2(bx, t - 1, b2, length);
            finalize_row(bx, t - 1, bout, out);
        }
        gsync(epoch);

        // P2: cell layer0 (z_lm1 = 1)
        cell_hm(bx, 0, t, xt + bx * H, Ht1 + bx * H,
                g_zw[0], g_zw[1], g_zw[2], bz0, b0, length, 1.0f, red);
        gsync(epoch);

        // P3: GEMM layer1 (Z0 new scales bottom, Z1 old scales top)
        seg_gemm(Ht1, nullptr, Ht0, g_Z, Ht2, g_Z + B,
                 g_W6[3], g_W6[4], g_W6[5], 4096, ntB * 256, ksB * 12, ksB * 12 + 12,
                 g_preP[ksB], 4096, As2, Bs0);
        gsync(epoch);

        // P4: cell layer1 (z_lm1 = Z0 new)
        cell_hm(bx, 1, t, Ht0 + bx * H, Ht2 + bx * H,
                g_zw[3], g_zw[4], g_zw[5], bz1, b1, length, g_Z[bx], red);
        gsync(epoch);

        // P5: GEMM layer2 (2 segments, old Ht2 + new Ht1) + gate mixing
        seg_gemm(Ht2, nullptr, Ht1, nullptr, nullptr, nullptr,
                 Whh2, Wih2, nullptr, 4096, ntB * 256, ksB * 8, ksB * 8 + 8,
                 g_pre2P[ksB], 4096, As2, Bs0);
        gate_row(bx, Wgate, bgate, red);
        gsync(epoch);

        // P6: gated output mix (new Ht0/Ht1, OLD Ht2; scales = gate_flat[l*128+row])
        seg_gemm(Ht0, g_gate + 0, Ht1, g_gate + 128, Ht2, g_gate + 256,
                 Wout, Wout, Wout, 1024, ntO * 256, ksO * 3, ksO * 3 + 3,
                 g_outP[ksO], 1024, As2, Bs0);
        gsync(epoch);
    }

    // epilogue: commit last layer2 state + final output
    cell_l2(bx, TSTEPS - 1, b2, length);
    finalize_row(bx, TSTEPS - 1, bout, out);
}

// ------------------------- host -------------------------
extern "C" void kernel_launch(void* const* d_in, const int* in_sizes, int n_in,
                              void* d_out, int out_size)
{
    const float* input_ = (const float*)d_in[0];
    const int*   length = (const int*)d_in[1];
    const float* Wbh0 = (const float*)d_in[2];
    const float* Whh0 = (const float*)d_in[3];
    const float* Wth0 = (const float*)d_in[4];
    const float* b0   = (const float*)d_in[5];
    const float* Wbh1 = (const float*)d_in[6];
    const float* Whh1 = (const float*)d_in[7];
    const float* Wth1 = (const float*)d_in[8];
    const float* b1   = (const float*)d_in[9];
    const float* Wih2 = (const float*)d_in[10];
    const float* Whh2 = (const float*)d_in[11];
    const float* b2   = (const float*)d_in[12];
    const float* Wout = (const float*)d_in[13];
    const float* bout = (const float*)d_in[14];
    const float* Wgate = (const float*)d_in[15];
    const float* bgate = (const float*)d_in[16];
    float* out = (float*)d_out;

    static int smem_set = 0;
    if (!smem_set) {
        cudaFuncSetAttribute(hm_persist, cudaFuncAttributeMaxDynamicSharedMemorySize,
                             SMEM_FLOATS * (int)sizeof(float));
        smem_set = 1;
    }

    repack_kernel<<<dim3(4096, 6), 1024>>>(Whh0, Wbh0, Wth0, Whh1, Wbh1, Wth1);
    init_misc<<<768, 512>>>(Whh0, Wbh0, Wth0, Whh1, Wbh1, Wth1);
    hm_persist<<<NB, NT, SMEM_FLOATS * (int)sizeof(float)>>>(
        input_, length, b0, b1, Wih2, Whh2, b2, Wout, bout, Wgate, bgate, out);
}

// round 11
// speedup vs baseline: 1.0509x; 1.0207x over previous
#include <cuda_runtime.h>
#include <math.h>

typedef unsigned long long ull;

#define NB  128      // persistent CTAs
#define NT  512      // threads per CTA
#define TSTEPS 128
#define B   128
#define H   1024

#define AS2_PAD    260                    // floats per k-row of duplicated A
#define AS2_FLOATS (32 * AS2_PAD)         // 8320 (one stage)
#define BS_FLOATS  (32 * 256)             // 8192 (one stage)
#define SMEM_FLOATS (2 * AS2_FLOATS + 3 * BS_FLOATS)   // 41216 floats = 161 KB

// ------------------------- device state (no allocs allowed) -------------------------
__device__ float g_Ht[3 * B * H];
__device__ float g_C [3 * B * H];
__device__ float g_Z [2 * B];
__device__ float g_preP [8][B * 4096];   // k-split partials, layers 0/1
__device__ float g_pre2P[8][B * 4096];   // k-split partials, layer 2
__device__ float g_outP [32][B * H];     // k-split partials, output mix
__device__ float g_gate[3 * B];          // flat == gate.reshape(-1) (b-major, l inner)
__device__ float g_zw[6][H];             // z-columns: hh0,bh0,th0,hh1,bh1,th1
__device__ float g_W6[6][1024 * 4096];   // repacked weights (z-col dropped, ldw=4096)
__device__ unsigned          g_count;
__device__ volatile unsigned g_release;

// ------------------------- helpers -------------------------
__device__ __forceinline__ ull pk2(float x, float y) {
    ull r; asm("mov.b64 %0, {%1, %2};" : "=l"(r) : "f"(x), "f"(y)); return r;
}
__device__ __forceinline__ ull fma2(ull a, ull b, ull c) {
    ull d; asm("fma.rn.f32x2 %0, %1, %2, %3;" : "=l"(d) : "l"(a), "l"(b), "l"(c)); return d;
}
__device__ __forceinline__ float sigf(float x) { return 1.0f / (1.0f + expf(-x)); }

__device__ __forceinline__ void cp_async16(float* smem_dst, const float* gsrc) {
    unsigned s = (unsigned)__cvta_generic_to_shared(smem_dst);
    asm volatile("cp.async.cg.shared.global [%0], [%1], 16;" :: "r"(s), "l"(gsrc));
}
#define CP_COMMIT() asm volatile("cp.async.commit_group;" ::: "memory")
#define CP_WAIT0()  asm volatile("cp.async.wait_group 0;" ::: "memory")
#define CP_WAIT1()  asm volatile("cp.async.wait_group 1;" ::: "memory")

// ------------------------- grid barrier (all 128 CTAs resident) -------------------------
__device__ __forceinline__ void gsync(unsigned& epoch) {
    __syncthreads();
    if (threadIdx.x == 0) {
        epoch++;
        __threadfence();
        unsigned prev = atomicAdd(&g_count, 1u);
        if (prev == epoch * (unsigned)gridDim.x - 1u) {
            g_release = epoch;
        } else {
            while (g_release < epoch) { }   // tight spin (L2 poll)
        }
        __threadfence();
    }
    __syncthreads();
}

// static shared scratch
__shared__ ull   s_ptab[8];
__shared__ float s_red[64];

// ------------------------- segmented GEMM phase -------------------------
// out[r, n] = sum over chunks [c0,c1) of sc_seg[r] * A_seg[r,k] * W_seg[k,n]
// chunk c: seg = c>>5, k within segment = (c&31)*32. BM=128, BN=256, BK=32.
// 512 threads; thread tile 8 rows x (4 + 4) cols; acc packed along N (f32x2).
__device__ void seg_gemm(const float* A0, const float* sc0,
                         const float* A1, const float* sc1,
                         const float* A2, const float* sc2,
                         const float* W0, const float* W1, const float* W2,
                         int ldw, int n0, int c0, int c1,
                         float* outp, int ldo,
                         float* As2, float* Bs0)
{
    const int tid  = threadIdx.x;
    const int tr8  = (tid >> 5) << 3;   // warp id * 8 : 8 output rows (warp-uniform)
    const int tc4  = (tid & 31) << 2;   // cols tc4..+3 and 128+tc4..+3
    const int rowA = tid >> 3;          // A-load rows: rowA, rowA+64
    const int kg   = tid & 7;           // A-load k-group (4 floats)

    // park base pointers in smem so they are not live in registers all phase
    if (tid == 0) {
        s_ptab[0] = (ull)A0; s_ptab[1] = (ull)A1; s_ptab[2] = (ull)A2;
        s_ptab[3] = (ull)W0; s_ptab[4] = (ull)W1; s_ptab[5] = (ull)W2;
    }
    // per-row scales (2 rows per thread, 3 segments) — computed before args die
    float sv[3][2];
    sv[0][0] = sc0 ? sc0[rowA] : 1.0f;  sv[0][1] = sc0 ? sc0[rowA + 64] : 1.0f;
    sv[1][0] = sc1 ? sc1[rowA] : 1.0f;  sv[1][1] = sc1 ? sc1[rowA + 64] : 1.0f;
    sv[2][0] = sc2 ? sc2[rowA] : 1.0f;  sv[2][1] = sc2 ? sc2[rowA + 64] : 1.0f;
    __syncthreads();

    ull acc[8][4];
#pragma unroll
    for (int r = 0; r < 8; r++)
#pragma unroll
        for (int c = 0; c < 4; c++) acc[r][c] = 0ull;

    float4 aR[2];

    auto issueB = [&](int c, int stage) {
        const int seg = c >> 5;
        const int kl  = (c & 31) << 5;
        const float* W = reinterpret_cast<const float*>(s_ptab[3 + seg]);
        float* bdst = Bs0 + stage * BS_FLOATS;
#pragma unroll
        for (int p = 0; p < 4; p++) {
            int idx = tid + (p << 9);
            int kk = idx >> 6, n4 = (idx & 63) << 2;
            cp_async16(bdst + (kk << 8) + n4, W + (size_t)(kl + kk) * ldw + n0 + n4);
        }
        CP_COMMIT();
    };
    auto loadA = [&](int c) {
        const int seg = c >> 5;
        const int kl  = (c & 31) << 5;
        const float* A = reinterpret_cast<const float*>(s_ptab[seg]);
#pragma unroll
        for (int p = 0; p < 2; p++) {
            int row = rowA + (p << 6);
            float4 v = *reinterpret_cast<const float4*>(A + row * 1024 + kl + (kg << 2));
            float s2 = sv[seg][p];
            v.x *= s2; v.y *= s2; v.z *= s2; v.w *= s2;
            aR[p] = v;
        }
    };
    auto storeA = [&](int sA) {
        float* ab = As2 + sA * AS2_FLOATS;
#pragma unroll
        for (int p = 0; p < 2; p++) {
            int row2 = (rowA + (p << 6)) << 1;
            float4 v = aR[p];
            *reinterpret_cast<ull*>(ab + (kg * 4 + 0) * AS2_PAD + row2) = pk2(v.x, v.x);
            *reinterpret_cast<ull*>(ab + (kg * 4 + 1) * AS2_PAD + row2) = pk2(v.y, v.y);
            *reinterpret_cast<ull*>(ab + (kg * 4 + 2) * AS2_PAD + row2) = pk2(v.z, v.z);
            *reinterpret_cast<ull*>(ab + (kg * 4 + 3) * AS2_PAD + row2) = pk2(v.w, v.w);
        }
    };
    auto compute = [&](int sA, int sB) {
        const float* ab = As2 + sA * AS2_FLOATS + (tr8 << 1);
        const float* bb = Bs0 + sB * BS_FLOATS + tc4;
#pragma unroll 4
        for (int k = 0; k < 32; k++) {
            const float* arow = ab + k * AS2_PAD;
            ulonglong2 a01 = *reinterpret_cast<const ulonglong2*>(arow);
            ulonglong2 a23 = *reinterpret_cast<const ulonglong2*>(arow + 4);
            ulonglong2 a45 = *reinterpret_cast<const ulonglong2*>(arow + 8);
            ulonglong2 a67 = *reinterpret_cast<const ulonglong2*>(arow + 12);
            ulonglong2 b0  = *reinterpret_cast<const ulonglong2*>(bb + (k << 8));
            ulonglong2 b1  = *reinterpret_cast<const ulonglong2*>(bb + (k << 8) + 128);
            acc[0][0] = fma2(a01.x, b0.x, acc[0][0]);
            acc[0][1] = fma2(a01.x, b0.y, acc[0][1]);
            acc[0][2] = fma2(a01.x, b1.x, acc[0][2]);
            acc[0][3] = fma2(a01.x, b1.y, acc[0][3]);
            acc[1][0] = fma2(a01.y, b0.x, acc[1][0]);
            acc[1][1] = fma2(a01.y, b0.y, acc[1][1]);
            acc[1][2] = fma2(a01.y, b1.x, acc[1][2]);
            acc[1][3] = fma2(a01.y, b1.y, acc[1][3]);
            acc[2][0] = fma2(a23.x, b0.x, acc[2][0]);
            acc[2][1] = fma2(a23.x, b0.y, acc[2][1]);
            acc[2][2] = fma2(a23.x, b1.x, acc[2][2]);
            acc[2][3] = fma2(a23.x, b1.y, acc[2][3]);
            acc[3][0] = fma2(a23.y, b0.x, acc[3][0]);
            acc[3][1] = fma2(a23.y, b0.y, acc[3][1]);
            acc[3][2] = fma2(a23.y, b1.x, acc[3][2]);
            acc[3][3] = fma2(a23.y, b1.y, acc[3][3]);
            acc[4][0] = fma2(a45.x, b0.x, acc[4][0]);
            acc[4][1] = fma2(a45.x, b0.y, acc[4][1]);
            acc[4][2] = fma2(a45.x, b1.x, acc[4][2]);
            acc[4][3] = fma2(a45.x, b1.y, acc[4][3]);
            acc[5][0] = fma2(a45.y, b0.x, acc[5][0]);
            acc[5][1] = fma2(a45.y, b0.y, acc[5][1]);
            acc[5][2] = fma2(a45.y, b1.x, acc[5][2]);
            acc[5][3] = fma2(a45.y, b1.y, acc[5][3]);
            acc[6][0] = fma2(a67.x, b0.x, acc[6][0]);
            acc[6][1] = fma2(a67.x, b0.y, acc[6][1]);
            acc[6][2] = fma2(a67.x, b1.x, acc[6][2]);
            acc[6][3] = fma2(a67.x, b1.y, acc[6][3]);
            acc[7][0] = fma2(a67.y, b0.x, acc[7][0]);
            acc[7][1] = fma2(a67.y, b0.y, acc[7][1]);
            acc[7][2] = fma2(a67.y, b1.x, acc[7][2]);
            acc[7][3] = fma2(a67.y, b1.y, acc[7][3]);
        }
    };

    // prologue: chunk c0
    issueB(c0, 0);
    loadA(c0);
    storeA(0);

    int sA = 0, bi = 0;
    for (int c = c0; c < c1; c++) {
        bool more = (c + 1 < c1);
        int bnext = (bi == 2) ? 0 : bi + 1;
        if (more) { issueB(c + 1, bnext); loadA(c + 1); }
        if (more) CP_WAIT1(); else CP_WAIT0();
        __syncthreads();
        compute(sA, bi);
        if (more) { storeA(sA ^ 1); sA ^= 1; bi = bnext; }
    }

    // epilogue
#pragma unroll
    for (int r = 0; r < 8; r++) {
        float* o = outp + (size_t)(tr8 + r) * ldo + n0;
        *reinterpret_cast<ulonglong2*>(o + tc4)       = make_ulonglong2(acc[r][0], acc[r][1]);
        *reinterpret_cast<ulonglong2*>(o + 128 + tc4) = make_ulonglong2(acc[r][2], acc[r][3]);
    }
}

// ------------------------- 3-way reduction (shuffle + smem) -------------------------
__device__ __forceinline__ float wred(float v) {
    v += __shfl_xor_sync(0xffffffffu, v, 16);
    v += __shfl_xor_sync(0xffffffffu, v, 8);
    v += __shfl_xor_sync(0xffffffffu, v, 4);
    v += __shfl_xor_sync(0xffffffffu, v, 2);
    v += __shfl_xor_sync(0xffffffffu, v, 1);
    return v;
}
__device__ void red3(float s0, float s1, float s2, float& r0, float& r1, float& r2)
{
    s0 = wred(s0); s1 = wred(s1); s2 = wred(s2);
    const int w = threadIdx.x >> 5, lane = threadIdx.x & 31;
    if (lane == 0) { s_red[w] = s0; s_red[16 + w] = s1; s_red[32 + w] = s2; }
    __syncthreads();
    if (threadIdx.x < 3) {
        float v = 0.f;
#pragma unroll
        for (int i = 0; i < 16; i++) v += s_red[threadIdx.x * 16 + i];
        s_red[48 + threadIdx.x] = v;
    }
    __syncthreads();
    r0 = s_red[48]; r1 = s_red[49]; r2 = s_red[50];
    __syncthreads();
}

// ------------------------- HMLSTM cell (one CTA = one batch row) -------------------------
__device__ void cell_hm(int b, int l, int t,
                        const float* xb, const float* xtop,
                        const float* zw_hh, const float* zw_bh, const float* zw_th,
                        float bz, const float* bias,
                        const int* length, float z_lm1)
{
    const int tid = threadIdx.x;
    float* hrow = g_Ht + (l * B + b) * H;
    float* crow = g_C  + (l * B + b) * H;
    const float z_tm1 = g_Z[l * B + b];

    float s0 = 0.f, s1 = 0.f, s2 = 0.f;
    for (int k = tid; k < H; k += NT) {
        s0 += hrow[k] * zw_hh[k];
        s1 += xb[k]   * zw_bh[k];
        s2 += xtop[k] * zw_th[k];
    }
    float d0, d1, d2;
    red3(s0, s1, s2, d0, d1, d2);
    if (tid == 0) {
        float prez = d0 + bz + z_lm1 * d1 + z_tm1 * d2;
        // round-half-even(clip((z+1)/2,0,1)) == (z > 0)
        g_Z[l * B + b] = (prez > 0.0f) ? 1.0f : 0.0f;
    }

    const float tm   = (t < length[b]) ? 1.0f : 0.0f;
    const float keep = 1.0f - z_tm1;
    const float cp   = (1.0f - z_tm1) * (1.0f - z_lm1);

    for (int h = tid; h < H; h += NT) {
        float f = bias[h], i = bias[1024 + h], o = bias[2048 + h], g = bias[3072 + h];
#pragma unroll
        for (int p = 0; p < 8; p++) {
            const float* P = g_preP[p] + b * 4096;
            f += P[h]; i += P[1024 + h]; o += P[2048 + h]; g += P[3072 + h];
        }
        float c_old = crow[h], h_old = hrow[h];
        float c1 = keep * sigf(f) * c_old + sigf(i) * tanhf(g);
        float h1 = sigf(o) * tanhf(c1);
        float hn = cp * h_old + (1.0f - cp) * h1;
        float cn = cp * c_old + (1.0f - cp) * c1;
        hrow[h] = tm * hn + (1.0f - tm) * h_old;
        crow[h] = tm * cn + (1.0f - tm) * c_old;
    }
}

// plain LSTM (layer 2) commit
__device__ void cell_l2(int b, int t, const float* bias, const int* length)
{
    const int tid = threadIdx.x;
    float* hrow = g_Ht + (2 * B + b) * H;
    float* crow = g_C  + (2 * B + b) * H;
    const float cp = 1.0f - g_Z[b];     // z_tm1=0, z_lm1=Z0(new)
    const float tm = (t < length[b]) ? 1.0f : 0.0f;

    for (int h = tid; h < H; h += NT) {
        float f = bias[h], i = bias[1024 + h], o = bias[2048 + h], g = bias[3072 + h];
#pragma unroll
        for (int p = 0; p < 8; p++) {
            const float* P = g_pre2P[p] + b * 4096;
            f += P[h]; i += P[1024 + h]; o += P[2048 + h]; g += P[3072 + h];
        }
        float c_old = crow[h], h_old = hrow[h];
        float c1 = sigf(f) * c_old + sigf(i) * tanhf(g);
        float h1 = sigf(o) * tanhf(c1);
        float hn = cp * h_old + (1.0f - cp) * h1;
        float cn = cp * c_old + (1.0f - cp) * c1;
        hrow[h] = tm * hn + (1.0f - tm) * h_old;
        crow[h] = tm * cn + (1.0f - tm) * c_old;
    }
}

// gate[b][l] = sigmoid( Ht.reshape(B,3H)[b] . Wgate[:,l] + bgate[l] )
__device__ void gate_row(int b, const float* Wgate, const float* bgate)
{
    const int tid = threadIdx.x;
    float s0 = 0.f, s1 = 0.f, s2 = 0.f;
    const float* hb = g_Ht + b * 3072;   // flat view == reshape(B, L*H) row b
    for (int j = tid; j < 3072; j += NT) {
        float h = hb[j];
        s0 += h * Wgate[j * 3 + 0];
        s1 += h * Wgate[j * 3 + 1];
        s2 += h * Wgate[j * 3 + 2];
    }
    float d0, d1, d2;
    red3(s0, s1, s2, d0, d1, d2);
    if (tid == 0) {
        g_gate[b * 3 + 0] = sigf(d0 + bgate[0]);
        g_gate[b * 3 + 1] = sigf(d1 + bgate[1]);
        g_gate[b * 3 + 2] = sigf(d2 + bgate[2]);
    }
}

// out[t,b,:] = sum_32 partials + (gate_flat[b]+gate_flat[128+b]+gate_flat[256+b]) * bout
__device__ void finalize_row(int b, int t, const float* bout, float* out)
{
    const int tid = threadIdx.x;
    const float gs = g_gate[b] + g_gate[128 + b] + g_gate[256 + b];
    float* o = out + ((size_t)t * B + b) * H;
    for (int h = tid; h < H; h += NT) {
        float s = gs * bout[h];
#pragma unroll
        for (int p = 0; p < 32; p++) s += g_outP[p][b * H + h];
        o[h] = s;
    }
}

// ------------------------- init kernels -------------------------
__global__ void __launch_bounds__(1024)
repack_kernel(const float* Whh0, const float* Wbh0, const float* Wth0,
              const float* Whh1, const float* Wbh1, const float* Wth1)
{
    const float* srcs[6] = {Whh0, Wbh0, Wth0, Whh1, Wbh1, Wth1};
    int slab = blockIdx.y;
    int idx = blockIdx.x * 1024 + threadIdx.x;     // 0 .. 4194303
    int k = idx >> 12, n = idx & 4095;
    g_W6[slab][idx] = srcs[slab][(size_t)k * 4097 + n];
}

__global__ void __launch_bounds__(512)
init_misc(const float* Whh0, const float* Wbh0, const float* Wth0,
          const float* Whh1, const float* Wbh1, const float* Wth1)
{
    int idx = blockIdx.x * blockDim.x + threadIdx.x;
    for (int i = idx; i < 3 * B * H; i += gridDim.x * blockDim.x) {
        g_Ht[i] = 0.f; g_C[i] = 0.f;
    }
    if (idx < 2 * B) g_Z[idx] = 0.f;
    if (idx < H) {
        g_zw[0][idx] = Whh0[(size_t)idx * 4097 + 4096];
        g_zw[1][idx] = Wbh0[(size_t)idx * 4097 + 4096];
        g_zw[2][idx] = Wth0[(size_t)idx * 4097 + 4096];
        g_zw[3][idx] = Whh1[(size_t)idx * 4097 + 4096];
        g_zw[4][idx] = Wbh1[(size_t)idx * 4097 + 4096];
        g_zw[5][idx] = Wth1[(size_t)idx * 4097 + 4096];
    }
    if (idx == 0) { g_count = 0; g_release = 0; }
}

// ------------------------- persistent kernel -------------------------
__global__ void __launch_bounds__(NT, 1)
hm_persist(const float* __restrict__ input_, const int* __restrict__ length,
           const float* __restrict__ b0,   const float* __restrict__ b1,
           const float* __restrict__ Wih2, const float* __restrict__ Whh2,
           const float* __restrict__ b2,   const float* __restrict__ Wout,
           const float* __restrict__ bout, const float* __restrict__ Wgate,
           const float* __restrict__ bgate, float* __restrict__ out)
{
    extern __shared__ float smem[];
    float* As2 = smem;                       // 2 stages
    float* Bs0 = smem + 2 * AS2_FLOATS;      // 3 stages

    const int bx = blockIdx.x;
    unsigned epoch = 0;

    const int ntB = bx >> 3, ksB = bx & 7;    // N=4096: 16 n-tiles x 8 k-splits
    const int ntO = bx & 3,  ksO = bx >> 2;   // N=1024: 4 n-tiles x 32 k-splits

    const float* Ht0 = g_Ht;
    const float* Ht1 = g_Ht + B * H;
    const float* Ht2 = g_Ht + 2 * B * H;

    const float bz0 = b0[4096];
    const float bz1 = b1[4096];

    for (int t = 0; t < TSTEPS; t++) {
        const float* xt = input_ + (size_t)t * B * H;

        // P1: GEMM layer0 (+ tail: commit layer2 of t-1, finalize output of t-1)
        seg_gemm(Ht0, nullptr, xt, nullptr, Ht1, g_Z,
                 g_W6[0], g_W6[1], g_W6[2], 4096, ntB * 256, ksB * 12, ksB * 12 + 12,
                 g_preP[ksB], 4096, As2, Bs0);
        if (t > 0) {
            cell_l2(bx, t - 1, b2, length);
            finalize_row(bx, t - 1, bout, out);
        }
        gsync(epoch);

        // P2: cell layer0 (z_lm1 = 1)
        cell_hm(bx, 0, t, xt + bx * H, Ht1 + bx * H,
                g_zw[0], g_zw[1], g_zw[2], bz0, b0, length, 1.0f);
        gsync(epoch);

        // P3: GEMM layer1 (Z0 new scales bottom, Z1 old scales top)
        seg_gemm(Ht1, nullptr, Ht0, g_Z, Ht2, g_Z + B,
                 g_W6[3], g_W6[4], g_W6[5], 4096, ntB * 256, ksB * 12, ksB * 12 + 12,
                 g_preP[ksB], 4096, As2, Bs0);
        gsync(epoch);

        // P4: cell layer1 (z_lm1 = Z0 new)
        cell_hm(bx, 1, t, Ht0 + bx * H, Ht2 + bx * H,
                g_zw[3], g_zw[4], g_zw[5], bz1, b1, length, g_Z[bx]);
        gsync(epoch);

        // P5: GEMM layer2 (2 segments, old Ht2 + new Ht1) + gate mixing
        seg_gemm(Ht2, nullptr, Ht1, nullptr, nullptr, nullptr,
                 Whh2, Wih2, nullptr, 4096, ntB * 256, ksB * 8, ksB * 8 + 8,
                 g_pre2P[ksB], 4096, As2, Bs0);
        gate_row(bx, Wgate, bgate);
        gsync(epoch);

        // P6: gated output mix (new Ht0/Ht1, OLD Ht2; scales = gate_flat[l*128+row])
        seg_gemm(Ht0, g_gate + 0, Ht1, g_gate + 128, Ht2, g_gate + 256,
                 Wout, Wout, Wout, 1024, ntO * 256, ksO * 3, ksO * 3 + 3,
                 g_outP[ksO], 1024, As2, Bs0);
        gsync(epoch);
    }

    // epilogue: commit last layer2 state + final output
    cell_l2(bx, TSTEPS - 1, b2, length);
    finalize_row(bx, TSTEPS - 1, bout, out);
}

// ------------------------- host -------------------------
extern "C" void kernel_launch(void* const* d_in, const int* in_sizes, int n_in,
                              void* d_out, int out_size)
{
    const float* input_ = (const float*)d_in[0];
    const int*   length = (const int*)d_in[1];
    const float* Wbh0 = (const float*)d_in[2];
    const float* Whh0 = (const float*)d_in[3];
    const float* Wth0 = (const float*)d_in[4];
    const float* b0   = (const float*)d_in[5];
    const float* Wbh1 = (const float*)d_in[6];
    const float* Whh1 = (const float*)d_in[7];
    const float* Wth1 = (const float*)d_in[8];
    const float* b1   = (const float*)d_in[9];
    const float* Wih2 = (const float*)d_in[10];
    const float* Whh2 = (const float*)d_in[11];
    const float* b2   = (const float*)d_in[12];
    const float* Wout = (const float*)d_in[13];
    const float* bout = (const float*)d_in[14];
    const float* Wgate = (const float*)d_in[15];
    const float* bgate = (const float*)d_in[16];
    float* out = (float*)d_out;

    static int smem_set = 0;
    if (!smem_set) {
        cudaFuncSetAttribute(hm_persist, cudaFuncAttributeMaxDynamicSharedMemorySize,
                             SMEM_FLOATS * (int)sizeof(float));
        smem_set = 1;
    }

    repack_kernel<<<dim3(4096, 6), 1024>>>(Whh0, Wbh0, Wth0, Whh1, Wbh1, Wth1);
    init_misc<<<768, 512>>>(Whh0, Wbh0, Wth0, Whh1, Wbh1, Wth1);
    hm_persist<<<NB, NT, SMEM_FLOATS * (int)sizeof(float)>>>(
        input_, length, b0, b1, Wih2, Whh2, b2, Wout, bout, Wgate, bgate, out);
}

// round 12
// speedup vs baseline: 1.0536x; 1.0026x over previous
#include <cuda_runtime.h>
#include <math.h>

typedef unsigned long long ull;

#define NB  128      // persistent CTAs
#define NT  512      // threads per CTA
#define TSTEPS 128
#define B   128
#define H   1024

#define AS2_PAD    260                    // floats per k-row of duplicated A
#define AS2_FLOATS (32 * AS2_PAD)         // 8320 (one stage)
#define BS_FLOATS  (32 * 256)             // 8192 (one stage)
#define SMEM_FLOATS (2 * AS2_FLOATS + 3 * BS_FLOATS)   // 41216 floats = 161 KB

// ------------------------- device state (no allocs allowed) -------------------------
__device__ float g_Ht[3 * B * H];
__device__ float g_C [3 * B * H];
__device__ float g_Z [2 * B];
__device__ float g_preP [8][B * 4096];   // k-split partials, layers 0/1
__device__ float g_pre2P[8][B * 4096];   // k-split partials, layer 2
__device__ float g_outP [32][B * H];     // k-split partials, output mix
__device__ float g_gate[3 * B];          // flat == gate.reshape(-1) (b-major, l inner)
__device__ float g_zw[6][H];             // z-columns: hh0,bh0,th0,hh1,bh1,th1
__device__ float g_W6[6][1024 * 4096];   // repacked weights (z-col dropped, ldw=4096)
__device__ unsigned          g_count;
__device__ volatile unsigned g_release;

// ------------------------- helpers -------------------------
__device__ __forceinline__ ull pk2(float x, float y) {
    ull r; asm("mov.b64 %0, {%1, %2};" : "=l"(r) : "f"(x), "f"(y)); return r;
}
__device__ __forceinline__ ull fma2(ull a, ull b, ull c) {
    ull d; asm("fma.rn.f32x2 %0, %1, %2, %3;" : "=l"(d) : "l"(a), "l"(b), "l"(c)); return d;
}
__device__ __forceinline__ float sigf(float x) { return 1.0f / (1.0f + expf(-x)); }

__device__ __forceinline__ void cp_async16(float* smem_dst, const float* gsrc) {
    unsigned s = (unsigned)__cvta_generic_to_shared(smem_dst);
    asm volatile("cp.async.cg.shared.global [%0], [%1], 16;" :: "r"(s), "l"(gsrc));
}
#define CP_COMMIT() asm volatile("cp.async.commit_group;" ::: "memory")
#define CP_WAIT0()  asm volatile("cp.async.wait_group 0;" ::: "memory")
#define CP_WAIT1()  asm volatile("cp.async.wait_group 1;" ::: "memory")

// ------------------------- grid barrier (all 128 CTAs resident) -------------------------
__device__ __forceinline__ void gsync(unsigned& epoch) {
    __syncthreads();
    if (threadIdx.x == 0) {
        epoch++;
        __threadfence();
        unsigned prev = atomicAdd(&g_count, 1u);
        if (prev == epoch * (unsigned)gridDim.x - 1u) {
            g_release = epoch;
        } else {
            while (g_release < epoch) { }   // tight spin (L2 poll)
        }
        __threadfence();
    }
    __syncthreads();
}

// static shared scratch
__shared__ ull   s_ptab[8];
__shared__ float s_red[64];

// ------------------------- segmented GEMM phase -------------------------
// out[r, n] = sum over chunks [c0,c1) of sc_seg[r] * A_seg[r,k] * W_seg[k,n]
// chunk c: seg = c>>5, k within segment = (c&31)*32. BM=128, BN=256, BK=32.
// 512 threads; thread tile 8 rows x (4 + 4) cols; acc packed along N (f32x2).
__device__ void seg_gemm(const float* A0, const float* sc0,
                         const float* A1, const float* sc1,
                         const float* A2, const float* sc2,
                         const float* W0, const float* W1, const float* W2,
                         int ldw, int n0, int c0, int c1,
                         float* outp, int ldo,
                         float* As2, float* Bs0)
{
    const int tid  = threadIdx.x;
    const int tr8  = (tid >> 5) << 3;   // warp id * 8 : 8 output rows (warp-uniform)
    const int tc4  = (tid & 31) << 2;   // cols tc4..+3 and 128+tc4..+3
    const int rowA = tid >> 3;          // A-load rows: rowA, rowA+64
    const int kg   = tid & 7;           // A-load k-group (4 floats)

    // park base pointers in smem so they are not live in registers all phase
    if (tid == 0) {
        s_ptab[0] = (ull)A0; s_ptab[1] = (ull)A1; s_ptab[2] = (ull)A2;
        s_ptab[3] = (ull)W0; s_ptab[4] = (ull)W1; s_ptab[5] = (ull)W2;
    }
    // per-row scales (2 rows per thread, 3 segments) — computed before args die
    float sv[3][2];
    sv[0][0] = sc0 ? sc0[rowA] : 1.0f;  sv[0][1] = sc0 ? sc0[rowA + 64] : 1.0f;
    sv[1][0] = sc1 ? sc1[rowA] : 1.0f;  sv[1][1] = sc1 ? sc1[rowA + 64] : 1.0f;
    sv[2][0] = sc2 ? sc2[rowA] : 1.0f;  sv[2][1] = sc2 ? sc2[rowA + 64] : 1.0f;
    __syncthreads();

    ull acc[8][4];
#pragma unroll
    for (int r = 0; r < 8; r++)
#pragma unroll
        for (int c = 0; c < 4; c++) acc[r][c] = 0ull;

    float4 aR[2];

    auto issueB = [&](int c, int stage) {
        const int seg = c >> 5;
        const int kl  = (c & 31) << 5;
        const float* W = reinterpret_cast<const float*>(s_ptab[3 + seg]);
        float* bdst = Bs0 + stage * BS_FLOATS;
#pragma unroll
        for (int p = 0; p < 4; p++) {
            int idx = tid + (p << 9);
            int kk = idx >> 6, n4 = (idx & 63) << 2;
            cp_async16(bdst + (kk << 8) + n4, W + (size_t)(kl + kk) * ldw + n0 + n4);
        }
        CP_COMMIT();
    };
    auto loadA = [&](int c) {
        const int seg = c >> 5;
        const int kl  = (c & 31) << 5;
        const float* A = reinterpret_cast<const float*>(s_ptab[seg]);
#pragma unroll
        for (int p = 0; p < 2; p++) {
            int row = rowA + (p << 6);
            float4 v = *reinterpret_cast<const float4*>(A + row * 1024 + kl + (kg << 2));
            float s2 = sv[seg][p];
            v.x *= s2; v.y *= s2; v.z *= s2; v.w *= s2;
            aR[p] = v;
        }
    };
    auto storeA = [&](int sA) {
        float* ab = As2 + sA * AS2_FLOATS;
#pragma unroll
        for (int p = 0; p < 2; p++) {
            int row2 = (rowA + (p << 6)) << 1;
            float4 v = aR[p];
            *reinterpret_cast<ull*>(ab + (kg * 4 + 0) * AS2_PAD + row2) = pk2(v.x, v.x);
            *reinterpret_cast<ull*>(ab + (kg * 4 + 1) * AS2_PAD + row2) = pk2(v.y, v.y);
            *reinterpret_cast<ull*>(ab + (kg * 4 + 2) * AS2_PAD + row2) = pk2(v.z, v.z);
            *reinterpret_cast<ull*>(ab + (kg * 4 + 3) * AS2_PAD + row2) = pk2(v.w, v.w);
        }
    };
    auto compute = [&](int sA, int sB) {
        const float* ab = As2 + sA * AS2_FLOATS + (tr8 << 1);
        const float* bb = Bs0 + sB * BS_FLOATS + tc4;
#pragma unroll 4
        for (int k = 0; k < 32; k++) {
            const float* arow = ab + k * AS2_PAD;
            ulonglong2 a01 = *reinterpret_cast<const ulonglong2*>(arow);
            ulonglong2 a23 = *reinterpret_cast<const ulonglong2*>(arow + 4);
            ulonglong2 a45 = *reinterpret_cast<const ulonglong2*>(arow + 8);
            ulonglong2 a67 = *reinterpret_cast<const ulonglong2*>(arow + 12);
            ulonglong2 b0  = *reinterpret_cast<const ulonglong2*>(bb + (k << 8));
            ulonglong2 b1  = *reinterpret_cast<const ulonglong2*>(bb + (k << 8) + 128);
            acc[0][0] = fma2(a01.x, b0.x, acc[0][0]);
            acc[0][1] = fma2(a01.x, b0.y, acc[0][1]);
            acc[0][2] = fma2(a01.x, b1.x, acc[0][2]);
            acc[0][3] = fma2(a01.x, b1.y, acc[0][3]);
            acc[1][0] = fma2(a01.y, b0.x, acc[1][0]);
            acc[1][1] = fma2(a01.y, b0.y, acc[1][1]);
            acc[1][2] = fma2(a01.y, b1.x, acc[1][2]);
            acc[1][3] = fma2(a01.y, b1.y, acc[1][3]);
            acc[2][0] = fma2(a23.x, b0.x, acc[2][0]);
            acc[2][1] = fma2(a23.x, b0.y, acc[2][1]);
            acc[2][2] = fma2(a23.x, b1.x, acc[2][2]);
            acc[2][3] = fma2(a23.x, b1.y, acc[2][3]);
            acc[3][0] = fma2(a23.y, b0.x, acc[3][0]);
            acc[3][1] = fma2(a23.y, b0.y, acc[3][1]);
            acc[3][2] = fma2(a23.y, b1.x, acc[3][2]);
            acc[3][3] = fma2(a23.y, b1.y, acc[3][3]);
            acc[4][0] = fma2(a45.x, b0.x, acc[4][0]);
            acc[4][1] = fma2(a45.x, b0.y, acc[4][1]);
            acc[4][2] = fma2(a45.x, b1.x, acc[4][2]);
            acc[4][3] = fma2(a45.x, b1.y, acc[4][3]);
            acc[5][0] = fma2(a45.y, b0.x, acc[5][0]);
            acc[5][1] = fma2(a45.y, b0.y, acc[5][1]);
            acc[5][2] = fma2(a45.y, b1.x, acc[5][2]);
            acc[5][3] = fma2(a45.y, b1.y, acc[5][3]);
            acc[6][0] = fma2(a67.x, b0.x, acc[6][0]);
            acc[6][1] = fma2(a67.x, b0.y, acc[6][1]);
            acc[6][2] = fma2(a67.x, b1.x, acc[6][2]);
            acc[6][3] = fma2(a67.x, b1.y, acc[6][3]);
            acc[7][0] = fma2(a67.y, b0.x, acc[7][0]);
            acc[7][1] = fma2(a67.y, b0.y, acc[7][1]);
            acc[7][2] = fma2(a67.y, b1.x, acc[7][2]);
            acc[7][3] = fma2(a67.y, b1.y, acc[7][3]);
        }
    };

    // prologue: chunk c0
    issueB(c0, 0);
    loadA(c0);
    storeA(0);

    int sA = 0, bi = 0;
    for (int c = c0; c < c1; c++) {
        bool more = (c + 1 < c1);
        int bnext = (bi == 2) ? 0 : bi + 1;
        if (more) { issueB(c + 1, bnext); loadA(c + 1); }
        if (more) CP_WAIT1(); else CP_WAIT0();
        __syncthreads();
        compute(sA, bi);
        if (more) { storeA(sA ^ 1); sA ^= 1; bi = bnext; }
    }

    // epilogue
#pragma unroll
    for (int r = 0; r < 8; r++) {
        float* o = outp + (size_t)(tr8 + r) * ldo + n0;
        *reinterpret_cast<ulonglong2*>(o + tc4)       = make_ulonglong2(acc[r][0], acc[r][1]);
        *reinterpret_cast<ulonglong2*>(o + 128 + tc4) = make_ulonglong2(acc[r][2], acc[r][3]);
    }
}

// ------------------------- 3-way reduction (shuffle + smem) -------------------------
__device__ __forceinline__ float wred(float v) {
    v += __shfl_xor_sync(0xffffffffu, v, 16);
    v += __shfl_xor_sync(0xffffffffu, v, 8);
    v += __shfl_xor_sync(0xffffffffu, v, 4);
    v += __shfl_xor_sync(0xffffffffu, v, 2);
    v += __shfl_xor_sync(0xffffffffu, v, 1);
    return v;
}
__device__ void red3(float s0, float s1, float s2, float& r0, float& r1, float& r2)
{
    s0 = wred(s0); s1 = wred(s1); s2 = wred(s2);
    const int w = threadIdx.x >> 5, lane = threadIdx.x & 31;
    if (lane == 0) { s_red[w] = s0; s_red[16 + w] = s1; s_red[32 + w] = s2; }
    __syncthreads();
    if (threadIdx.x < 3) {
        float v = 0.f;
#pragma unroll
        for (int i = 0; i < 16; i++) v += s_red[threadIdx.x * 16 + i];
        s_red[48 + threadIdx.x] = v;
    }
    __syncthreads();
    r0 = s_red[48]; r1 = s_red[49]; r2 = s_red[50];
    __syncthreads();
}

// ------------------------- HMLSTM cell (one CTA = one batch row) -------------------------
__device__ void cell_hm(int b, int l, int t,
                        const float* xb, const float* xtop,
                        const float* zw_hh, const float* zw_bh, const float* zw_th,
                        float bz, const float* bias,
                        const int* length, float z_lm1)
{
    const int tid = threadIdx.x;
    float* hrow = g_Ht + (l * B + b) * H;
    float* crow = g_C  + (l * B + b) * H;
    const float z_tm1 = g_Z[l * B + b];

    float s0 = 0.f, s1 = 0.f, s2 = 0.f;
    for (int k = tid; k < H; k += NT) {
        s0 += hrow[k] * zw_hh[k];
        s1 += xb[k]   * zw_bh[k];
        s2 += xtop[k] * zw_th[k];
    }
    float d0, d1, d2;
    red3(s0, s1, s2, d0, d1, d2);
    if (tid == 0) {
        float prez = d0 + bz + z_lm1 * d1 + z_tm1 * d2;
        // round-half-even(clip((z+1)/2,0,1)) == (z > 0)
        g_Z[l * B + b] = (prez > 0.0f) ? 1.0f : 0.0f;
    }

    const float tm   = (t < length[b]) ? 1.0f : 0.0f;
    const float keep = 1.0f - z_tm1;
    const float cp   = (1.0f - z_tm1) * (1.0f - z_lm1);

    for (int h = tid; h < H; h += NT) {
        float f = bias[h], i = bias[1024 + h], o = bias[2048 + h], g = bias[3072 + h];
#pragma unroll
        for (int p = 0; p < 8; p++) {
            const float* P = g_preP[p] + b * 4096;
            f += P[h]; i += P[1024 + h]; o += P[2048 + h]; g += P[3072 + h];
        }
        float c_old = crow[h], h_old = hrow[h];
        float c1 = keep * sigf(f) * c_old + sigf(i) * tanhf(g);
        float h1 = sigf(o) * tanhf(c1);
        float hn = cp * h_old + (1.0f - cp) * h1;
        float cn = cp * c_old + (1.0f - cp) * c1;
        hrow[h] = tm * hn + (1.0f - tm) * h_old;
        crow[h] = tm * cn + (1.0f - tm) * c_old;
    }
}

// plain LSTM (layer 2) commit
__device__ void cell_l2(int b, int t, const float* bias, const int* length)
{
    const int tid = threadIdx.x;
    float* hrow = g_Ht + (2 * B + b) * H;
    float* crow = g_C  + (2 * B + b) * H;
    const float cp = 1.0f - g_Z[b];     // z_tm1=0, z_lm1=Z0(new)
    const float tm = (t < length[b]) ? 1.0f : 0.0f;

    for (int h = tid; h < H; h += NT) {
        float f = bias[h], i = bias[1024 + h], o = bias[2048 + h], g = bias[3072 + h];
#pragma unroll
        for (int p = 0; p < 8; p++) {
            const float* P = g_pre2P[p] + b * 4096;
            f += P[h]; i += P[1024 + h]; o += P[2048 + h]; g += P[3072 + h];
        }
        float c_old = crow[h], h_old = hrow[h];
        float c1 = sigf(f) * c_old + sigf(i) * tanhf(g);
        float h1 = sigf(o) * tanhf(c1);
        float hn = cp * h_old + (1.0f - cp) * h1;
        float cn = cp * c_old + (1.0f - cp) * c1;
        hrow[h] = tm * hn + (1.0f - tm) * h_old;
        crow[h] = tm * cn + (1.0f - tm) * c_old;
    }
}

// gate[b][l] = sigmoid( Ht.reshape(B,3H)[b] . Wgate[:,l] + bgate[l] )
__device__ void gate_row(int b, const float* Wgate, const float* bgate)
{
    const int tid = threadIdx.x;
    float s0 = 0.f, s1 = 0.f, s2 = 0.f;
    const float* hb = g_Ht + b * 3072;   // flat view == reshape(B, L*H) row b
    for (int j = tid; j < 3072; j += NT) {
        float h = hb[j];
        s0 += h * Wgate[j * 3 + 0];
        s1 += h * Wgate[j * 3 + 1];
        s2 += h * Wgate[j * 3 + 2];
    }
    float d0, d1, d2;
    red3(s0, s1, s2, d0, d1, d2);
    if (tid == 0) {
        g_gate[b * 3 + 0] = sigf(d0 + bgate[0]);
        g_gate[b * 3 + 1] = sigf(d1 + bgate[1]);
        g_gate[b * 3 + 2] = sigf(d2 + bgate[2]);
    }
}

// out[t,b,:] = sum_32 partials + (gate_flat[b]+gate_flat[128+b]+gate_flat[256+b]) * bout
__device__ void finalize_row(int b, int t, const float* bout, float* out)
{
    const int tid = threadIdx.x;
    const float gs = g_gate[b] + g_gate[128 + b] + g_gate[256 + b];
    float* o = out + ((size_t)t * B + b) * H;
    for (int h = tid; h < H; h += NT) {
        float s = gs * bout[h];
#pragma unroll
        for (int p = 0; p < 32; p++) s += g_outP[p][b * H + h];
        o[h] = s;
    }
}

// ------------------------- init kernels -------------------------
__global__ void __launch_bounds__(1024)
repack_kernel(const float* Whh0, const float* Wbh0, const float* Wth0,
              const float* Whh1, const float* Wbh1, const float* Wth1)
{
    const float* srcs[6] = {Whh0, Wbh0, Wth0, Whh1, Wbh1, Wth1};
    int slab = blockIdx.y;
    int idx = blockIdx.x * 1024 + threadIdx.x;     // 0 .. 4194303
    int k = idx >> 12, n = idx & 4095;
    g_W6[slab][idx] = srcs[slab][(size_t)k * 4097 + n];
}

__global__ void __launch_bounds__(512)
init_misc(const float* Whh0, const float* Wbh0, const float* Wth0,
          const float* Whh1, const float* Wbh1, const float* Wth1)
{
    int idx = blockIdx.x * blockDim.x + threadIdx.x;
    for (int i = idx; i < 3 * B * H; i += gridDim.x * blockDim.x) {
        g_Ht[i] = 0.f; g_C[i] = 0.f;
    }
    if (idx < 2 * B) g_Z[idx] = 0.f;
    if (idx < H) {
        g_zw[0][idx] = Whh0[(size_t)idx * 4097 + 4096];
        g_zw[1][idx] = Wbh0[(size_t)idx * 4097 + 4096];
        g_zw[2][idx] = Wth0[(size_t)idx * 4097 + 4096];
        g_zw[3][idx] = Whh1[(size_t)idx * 4097 + 4096];
        g_zw[4][idx] = Wbh1[(size_t)idx * 4097 + 4096];
        g_zw[5][idx] = Wth1[(size_t)idx * 4097 + 4096];
    }
    if (idx == 0) { g_count = 0; g_release = 0; }
}

// ------------------------- persistent kernel -------------------------
__global__ void __launch_bounds__(NT, 1)
hm_persist(const float* __restrict__ input_, const int* __restrict__ length,
           const float* __restrict__ b0,   const float* __restrict__ b1,
           const float* __restrict__ Wih2, const float* __restrict__ Whh2,
           const float* __restrict__ b2,   const float* __restrict__ Wout,
           const float* __restrict__ bout, const float* __restrict__ Wgate,
           const float* __restrict__ bgate, float* __restrict__ out)
{
    extern __shared__ float smem[];
    float* As2 = smem;                       // 2 stages
    float* Bs0 = smem + 2 * AS2_FLOATS;      // 3 stages

    const int bx = blockIdx.x;
    unsigned epoch = 0;

    const int ntB = bx >> 3, ksB = bx & 7;    // N=4096: 16 n-tiles x 8 k-splits
    const int ntO = bx & 3,  ksO = bx >> 2;   // N=1024: 4 n-tiles x 32 k-splits

    const float* Ht0 = g_Ht;
    const float* Ht1 = g_Ht + B * H;
    const float* Ht2 = g_Ht + 2 * B * H;

    const float bz0 = b0[4096];
    const float bz1 = b1[4096];

    for (int t = 0; t < TSTEPS; t++) {
        const float* xt = input_ + (size_t)t * B * H;

        // P1: GEMM layer0 (+ tail: commit layer2 of t-1, finalize output of t-1)
        seg_gemm(Ht0, nullptr, xt, nullptr, Ht1, g_Z,
                 g_W6[0], g_W6[1], g_W6[2], 4096, ntB * 256, ksB * 12, ksB * 12 + 12,
                 g_preP[ksB], 4096, As2, Bs0);
        if (t > 0) {
            cell_l2(bx, t - 1, b2, length);
            finalize_row(bx, t - 1, bout, out);
        }
        gsync(epoch);

        // P2: cell layer0 (z_lm1 = 1)
        cell_hm(bx, 0, t, xt + bx * H, Ht1 + bx * H,
                g_zw[0], g_zw[1], g_zw[2], bz0, b0, length, 1.0f);
        gsync(epoch);

        // P3: GEMM layer1 (Z0 new scales bottom, Z1 old scales top)
        seg_gemm(Ht1, nullptr, Ht0, g_Z, Ht2, g_Z + B,
                 g_W6[3], g_W6[4], g_W6[5], 4096, ntB * 256, ksB * 12, ksB * 12 + 12,
                 g_preP[ksB], 4096, As2, Bs0);
        gsync(epoch);

        // P4: cell layer1 (z_lm1 = Z0 new)
        cell_hm(bx, 1, t, Ht0 + bx * H, Ht2 + bx * H,
                g_zw[3], g_zw[4], g_zw[5], bz1, b1, length, g_Z[bx]);
        gsync(epoch);

        // P5: GEMM layer2 (2 segments, old Ht2 + new Ht1) + gate mixing
        seg_gemm(Ht2, nullptr, Ht1, nullptr, nullptr, nullptr,
                 Whh2, Wih2, nullptr, 4096, ntB * 256, ksB * 8, ksB * 8 + 8,
                 g_pre2P[ksB], 4096, As2, Bs0);
        gate_row(bx, Wgate, bgate);
        gsync(epoch);

        // P6: gated output mix (new Ht0/Ht1, OLD Ht2; scales = gate_flat[l*128+row])
        seg_gemm(Ht0, g_gate + 0, Ht1, g_gate + 128, Ht2, g_gate + 256,
                 Wout, Wout, Wout, 1024, ntO * 256, ksO * 3, ksO * 3 + 3,
                 g_outP[ksO], 1024, As2, Bs0);
        gsync(epoch);
    }

    // epilogue: commit last layer2 state + final output
    cell_l2(bx, TSTEPS - 1, b2, length);
    finalize_row(bx, TSTEPS - 1, bout, out);
}

// ------------------------- host -------------------------
extern "C" void kernel_launch(void* const* d_in, const int* in_sizes, int n_in,
                              void* d_out, int out_size)
{
    const float* input_ = (const float*)d_in[0];
    const int*   length = (const int*)d_in[1];
    const float* Wbh0 = (const float*)d_in[2];
    const float* Whh0 = (const float*)d_in[3];
    const float* Wth0 = (const float*)d_in[4];
    const float* b0   = (const float*)d_in[5];
    const float* Wbh1 = (const float*)d_in[6];
    const float* Whh1 = (const float*)d_in[7];
    const float* Wth1 = (const float*)d_in[8];
    const float* b1   = (const float*)d_in[9];
    const float* Wih2 = (const float*)d_in[10];
    const float* Whh2 = (const float*)d_in[11];
    const float* b2   = (const float*)d_in[12];
    const float* Wout = (const float*)d_in[13];
    const float* bout = (const float*)d_in[14];
    const float* Wgate = (const float*)d_in[15];
    const float* bgate = (const float*)d_in[16];
    float* out = (float*)d_out;

    static int smem_set = 0;
    if (!smem_set) {
        cudaFuncSetAttribute(hm_persist, cudaFuncAttributeMaxDynamicSharedMemorySize,
                             SMEM_FLOATS * (int)sizeof(float));
        smem_set = 1;
    }

    repack_kernel<<<dim3(4096, 6), 1024>>>(Whh0, Wbh0, Wth0, Whh1, Wbh1, Wth1);
    init_misc<<<768, 512>>>(Whh0, Wbh0, Wth0, Whh1, Wbh1, Wth1);
    hm_persist<<<NB, NT, SMEM_FLOATS * (int)sizeof(float)>>>(
        input_, length, b0, b1, Wih2, Whh2, b2, Wout, bout, Wgate, bgate, out);
}

// round 14
// speedup vs baseline: 2.7712x; 2.6301x over previous
#include <cuda_runtime.h>
#include <cuda_fp16.h>
#include <math.h>

typedef unsigned long long ull;

#define NB 128
#define NT 512
#define TSTEPS 128
#define B 128
#define H 1024
#define SLAB (4096*1024)

// smem stage layout (bytes from 1024-aligned base): 3 stages
//   +0      A hi  16 KB (128 rows x 128B, SW128-swizzled)
//   +16384  A lo  16 KB
//   +32768  W hi   8 KB (64 rows x 128B)
//   +40960  W lo   8 KB
#define STAGE 49152
#define SMEM_BYTES (3 * STAGE + 1024)

// ------------------------- device state -------------------------
__device__ float g_Ht[3*B*H];
__device__ float g_C [3*B*H];
__device__ float g_Z [2*B];
__device__ float g_preP [2][B*4096];
__device__ float g_pre2P[2][B*4096];
__device__ float g_outP [8][B*H];
__device__ float g_gate[3*B];
__device__ float g_zw[6][H];
// half A-operand buffers, [22][B*H]:
// 0/1 h0 hi/lo   2/3 h1   4/5 h2   6/7 z0*h0   8/9 z0*h1   10/11 z1*h2
// 12/13 x par0   14/15 x par1   16/17 g0*h0   18/19 g1*h1   20/21 g2*h2
__device__ __half g_Ah[22][B*H];
__device__ __half g_Whi[8*SLAB + 1024*1024];   // transposed [n][k] hi halves
__device__ __half g_Wlo[8*SLAB + 1024*1024];   // transposed [n][k] lo halves
__device__ unsigned          g_count;
__device__ volatile unsigned g_release;

__shared__ float s_red[64];

// ------------------------- helpers -------------------------
__device__ __forceinline__ float sigf(float x) { return 1.0f / (1.0f + expf(-x)); }

__device__ __forceinline__ unsigned smem_u32(const void* p) {
    unsigned a;
    asm("{ .reg .u64 t; cvta.to.shared.u64 t, %1; cvt.u32.u64 %0, t; }" : "=r"(a) : "l"(p));
    return a;
}
__device__ __forceinline__ unsigned swz(unsigned off) { return off ^ ((off >> 3) & 0x70); }

__device__ __forceinline__ void cp16(unsigned saddr, const void* g) {
    asm volatile("cp.async.cg.shared.global [%0], [%1], 16;" :: "r"(saddr), "l"(g));
}
#define CP_COMMIT() asm volatile("cp.async.commit_group;" ::: "memory")
#define CP_WAIT0()  asm volatile("cp.async.wait_group 0;" ::: "memory")
#define CP_WAIT1()  asm volatile("cp.async.wait_group 1;" ::: "memory")

__device__ __forceinline__ void ldm4(unsigned* r, unsigned a) {
    asm volatile("ldmatrix.sync.aligned.m8n8.x4.shared.b16 {%0,%1,%2,%3}, [%4];"
                 : "=r"(r[0]), "=r"(r[1]), "=r"(r[2]), "=r"(r[3]) : "r"(a));
}
__device__ __forceinline__ void ldm2(unsigned* r, unsigned a) {
    asm volatile("ldmatrix.sync.aligned.m8n8.x2.shared.b16 {%0,%1}, [%2];"
                 : "=r"(r[0]), "=r"(r[1]) : "r"(a));
}
__device__ __forceinline__ void mma_fp16(float* c, const unsigned* a, const unsigned* b) {
    asm volatile("mma.sync.aligned.m16n8k16.row.col.f32.f16.f16.f32 "
                 "{%0,%1,%2,%3}, {%4,%5,%6,%7}, {%8,%9}, {%0,%1,%2,%3};"
                 : "+f"(c[0]), "+f"(c[1]), "+f"(c[2]), "+f"(c[3])
                 : "r"(a[0]), "r"(a[1]), "r"(a[2]), "r"(a[3]), "r"(b[0]), "r"(b[1]));
}

// exact 2-way fp16 split store
__device__ __forceinline__ void spl(__half* hi, __half* lo, int idx, float v) {
    __half h = __float2half_rn(v);
    hi[idx] = h;
    lo[idx] = __float2half_rn(v - __half2float(h));
}

// ------------------------- grid barrier -------------------------
__device__ __forceinline__ void gsync(unsigned& epoch) {
    __syncthreads();
    if (threadIdx.x == 0) {
        epoch++;
        __threadfence();
        unsigned prev = atomicAdd(&g_count, 1u);
        if (prev == epoch * (unsigned)gridDim.x - 1u) g_release = epoch;
        else while (g_release < epoch) { }
        __threadfence();
    }
    __syncthreads();
}

// ------------------------- HMMA segmented GEMM -------------------------
// D[0..127][n0..n0+64) = sum over chunks [c0,c1): chunk c: seg=c>>4, kl=(c&15)*64.
// A from precomputed hi/lo half buffers (row-major [B][1024]); W from g_Whi/g_Wlo
// (transposed [n][k]). fp16 split: Ah*Wh + Al*Wh + Ah*Wl, fp32 register accum.
__device__ void tc_gemm(const __half* A0h, const __half* A0l,
                        const __half* A1h, const __half* A1l,
                        const __half* A2h, const __half* A2l,
                        size_t w0, size_t w1, size_t w2,
                        int n0, int c0, int c1,
                        float* outp, int ldo, unsigned smb)
{
    const int tid = threadIdx.x;
    const int wid = tid >> 5, l = tid & 31;
    const int mb = (wid & 3) * 32;      // warp M base (4 warps in M)
    const int nb = (wid >> 2) * 16;     // warp N base (4 warps in N)

    // ldmatrix per-lane address row-parts (see PTX frag tables):
    // A x4: lanes 0-7 rows0-7(k0-7), 8-15 rows8-15, 16-23 rows0-7(k8-15), 24-31 rows8-15
    const unsigned arow = (unsigned)((mb + (l & 15)) * 128 + ((l >> 4) << 4));
    // B x2: lanes 0-7 rows n0-7 (k0-7), 8-15 rows n0-7 (k8-15)
    const unsigned brow = (unsigned)((nb + (l & 7)) * 128 + (((l >> 3) & 1) << 4));

    float acc[2][2][4];
#pragma unroll
    for (int i = 0; i < 2; i++)
#pragma unroll
        for (int j = 0; j < 2; j++)
#pragma unroll
            for (int q = 0; q < 4; q++) acc[i][j][q] = 0.0f;

    auto issue = [&](int c, int s) {
        const int seg = c >> 4;
        const int kl  = (c & 15) << 6;
        const __half* Ah = seg == 0 ? A0h : (seg == 1 ? A1h : A2h);
        const __half* Al = seg == 0 ? A0l : (seg == 1 ? A1l : A2l);
        const size_t  wo = seg == 0 ? w0 : (seg == 1 ? w1 : w2);
        const unsigned sb = smb + (unsigned)(s * STAGE);
#pragma unroll
        for (int p = 0; p < 2; p++) {          // A: 128 rows x 64 halves, hi+lo
            int idx = tid + (p << 9);
            int row = idx >> 3, cc = idx & 7;
            unsigned d = sb + swz((unsigned)(row * 128 + cc * 16));
            size_t go = (size_t)row * 1024 + kl + cc * 8;
            cp16(d, Ah + go);
            cp16(d + 16384, Al + go);
        }
        {                                       // W: 64 rows x 64 halves, hi+lo
            int row = tid >> 3, cc = tid & 7;
            unsigned d = sb + 32768 + swz((unsigned)(row * 128 + cc * 16));
            size_t go = wo + (size_t)(n0 + row) * 1024 + kl + cc * 8;
            cp16(d, g_Whi + go);
            cp16(d + 8192, g_Wlo + go);
        }
        CP_COMMIT();
    };

    auto compute = [&](int s) {
        const unsigned sb = smb + (unsigned)(s * STAGE);
#pragma unroll
        for (int ks = 0; ks < 4; ks++) {
            const unsigned ca = (unsigned)(ks * 32);
            unsigned ah0[4], ah1[4], al0[4], al1[4];
            unsigned bh0[2], bh1[2], bl0[2], bl1[2];
            ldm4(ah0, sb + swz(arow + ca));
            ldm4(ah1, sb + swz(arow + 2048 + ca));
            ldm4(al0, sb + 16384 + swz(arow + ca));
            ldm4(al1, sb + 16384 + swz(arow + 2048 + ca));
            ldm2(bh0, sb + 32768 + swz(brow + ca));
            ldm2(bh1, sb + 32768 + swz(brow + 1024 + ca));
            ldm2(bl0, sb + 40960 + swz(brow + ca));
            ldm2(bl1, sb + 40960 + swz(brow + 1024 + ca));
            mma_fp16(acc[0][0], ah0, bh0); mma_fp16(acc[0][1], ah0, bh1);
            mma_fp16(acc[1][0], ah1, bh0); mma_fp16(acc[1][1], ah1, bh1);
            mma_fp16(acc[0][0], al0, bh0); mma_fp16(acc[0][1], al0, bh1);
            mma_fp16(acc[1][0], al1, bh0); mma_fp16(acc[1][1], al1, bh1);
            mma_fp16(acc[0][0], ah0, bl0); mma_fp16(acc[0][1], ah0, bl1);
            mma_fp16(acc[1][0], ah1, bl0); mma_fp16(acc[1][1], ah1, bl1);
        }
    };

    issue(c0, 0);
    for (int c = c0; c < c1; c++) {
        int s = (c - c0) % 3;
        if (c + 1 < c1) { issue(c + 1, (s + 1) % 3); CP_WAIT1(); }
        else            { CP_WAIT0(); }
        __syncthreads();
        compute(s);
    }

    // epilogue: c0,c1 -> (row, col..col+1); c2,c3 -> row+8
#pragma unroll
    for (int fm = 0; fm < 2; fm++)
#pragma unroll
        for (int nf = 0; nf < 2; nf++) {
            int r0 = mb + fm * 16 + (l >> 2);
            int cc = n0 + nb + nf * 8 + (l & 3) * 2;
            float* o = outp + (size_t)r0 * ldo + cc;
            *reinterpret_cast<float2*>(o) = make_float2(acc[fm][nf][0], acc[fm][nf][1]);
            float* o2 = outp + (size_t)(r0 + 8) * ldo + cc;
            *reinterpret_cast<float2*>(o2) = make_float2(acc[fm][nf][2], acc[fm][nf][3]);
        }
}

// ------------------------- reductions -------------------------
__device__ __forceinline__ float wred(float v) {
    v += __shfl_xor_sync(0xffffffffu, v, 16);
    v += __shfl_xor_sync(0xffffffffu, v, 8);
    v += __shfl_xor_sync(0xffffffffu, v, 4);
    v += __shfl_xor_sync(0xffffffffu, v, 2);
    v += __shfl_xor_sync(0xffffffffu, v, 1);
    return v;
}
__device__ void red3(float s0, float s1, float s2, float& r0, float& r1, float& r2)
{
    s0 = wred(s0); s1 = wred(s1); s2 = wred(s2);
    const int w = threadIdx.x >> 5, lane = threadIdx.x & 31;
    if (lane == 0) { s_red[w] = s0; s_red[16 + w] = s1; s_red[32 + w] = s2; }
    __syncthreads();
    if (threadIdx.x < 3) {
        float v = 0.f;
#pragma unroll
        for (int i = 0; i < 16; i++) v += s_red[threadIdx.x * 16 + i];
        s_red[48 + threadIdx.x] = v;
    }
    __syncthreads();
    r0 = s_red[48]; r1 = s_red[49]; r2 = s_red[50];
    __syncthreads();
}

// ------------------------- cells (one CTA = one batch row) -------------------------
__device__ void cell_hm(int b, int lyr, int t,
                        const float* xb, const float* xtop,
                        const float* zw_hh, const float* zw_bh, const float* zw_th,
                        float bz, const float* bias, const int* length, float z_lm1,
                        __half* hhi, __half* hlo, __half* zhhi, __half* zhlo,
                        const float* xnext, __half* xnhi, __half* xnlo)
{
    const int tid = threadIdx.x;
    float* hrow = g_Ht + (lyr * B + b) * H;
    float* crow = g_C  + (lyr * B + b) * H;
    const float z_tm1 = g_Z[lyr * B + b];

    float s0 = 0.f, s1 = 0.f, s2 = 0.f;
    for (int k = tid; k < H; k += NT) {
        s0 += hrow[k] * zw_hh[k];
        s1 += xb[k]   * zw_bh[k];
        s2 += xtop[k] * zw_th[k];
    }
    float d0, d1, d2;
    red3(s0, s1, s2, d0, d1, d2);           // broadcast sums to all threads
    const float prez = d0 + bz + z_lm1 * d1 + z_tm1 * d2;
    const float znew = (prez > 0.0f) ? 1.0f : 0.0f;   // round-half-even == (z>0)
    if (tid == 0) g_Z[lyr * B + b] = znew;
    const float zs = (lyr == 0) ? znew : z_lm1;       // scale for z-scaled buffer

    const float tm   = (t < length[b]) ? 1.0f : 0.0f;
    const float keep = 1.0f - z_tm1;
    const float cp   = (1.0f - z_tm1) * (1.0f - z_lm1);
    const float* P0 = g_preP[0] + b * 4096;
    const float* P1 = g_preP[1] + b * 4096;

    for (int h = tid; h < H; h += NT) {
        float f = P0[h]        + P1[h]        + bias[h];
        float i = P0[1024 + h] + P1[1024 + h] + bias[1024 + h];
        float o = P0[2048 + h] + P1[2048 + h] + bias[2048 + h];
        float g = P0[3072 + h] + P1[3072 + h] + bias[3072 + h];
        float c_old = crow[h], h_old = hrow[h];
        float c1 = keep * sigf(f) * c_old + sigf(i) * tanhf(g);
        float h1 = sigf(o) * tanhf(c1);
        float hn = cp * h_old + (1.0f - cp) * h1;
        float cn = cp * c_old + (1.0f - cp) * c1;
        hn = tm * hn + (1.0f - tm) * h_old;
        cn = tm * cn + (1.0f - tm) * c_old;
        hrow[h] = hn;
        crow[h] = cn;
        spl(hhi + b * H, hlo + b * H, h, hn);
        spl(zhhi + b * H, zhlo + b * H, h, zs * hn);
        if (xnhi) spl(xnhi + b * H, xnlo + b * H, h, xnext[h]);
    }
}

__device__ void cell_l2(int b, int t, const float* bias, const int* length)
{
    const int tid = threadIdx.x;
    float* hrow = g_Ht + (2 * B + b) * H;
    float* crow = g_C  + (2 * B + b) * H;
    const float cp = 1.0f - g_Z[b];
    const float tm = (t < length[b]) ? 1.0f : 0.0f;
    const float zs = g_Z[B + b];            // z1_old for the upcoming step's P3
    const float* P0 = g_pre2P[0] + b * 4096;
    const float* P1 = g_pre2P[1] + b * 4096;

    for (int h = tid; h < H; h += NT) {
        float f = P0[h]        + P1[h]        + bias[h];
        float i = P0[1024 + h] + P1[1024 + h] + bias[1024 + h];
        float o = P0[2048 + h] + P1[2048 + h] + bias[2048 + h];
        float g = P0[3072 + h] + P1[3072 + h] + bias[3072 + h];
        float c_old = crow[h], h_old = hrow[h];
        float c1 = sigf(f) * c_old + sigf(i) * tanhf(g);
        float h1 = sigf(o) * tanhf(c1);
        float hn = cp * h_old + (1.0f - cp) * h1;
        float cn = cp * c_old + (1.0f - cp) * c1;
        hn = tm * hn + (1.0f - tm) * h_old;
        cn = tm * cn + (1.0f - tm) * c_old;
        hrow[h] = hn;
        crow[h] = cn;
        spl(g_Ah[4] + b * H, g_Ah[5] + b * H, h, hn);
        spl(g_Ah[10] + b * H, g_Ah[11] + b * H, h, zs * hn);
    }
}

__device__ void gate_row(int b, const float* Wgate, const float* bgate)
{
    const int tid = threadIdx.x;
    float s0 = 0.f, s1 = 0.f, s2 = 0.f;
    const float* hb = g_Ht + b * 3072;      // flat Ht.reshape(B, L*H) row b
    for (int j = tid; j < 3072; j += NT) {
        float h = hb[j];
        s0 += h * Wgate[j * 3 + 0];
        s1 += h * Wgate[j * 3 + 1];
        s2 += h * Wgate[j * 3 + 2];
    }
    float d0, d1, d2;
    red3(s0, s1, s2, d0, d1, d2);
    if (tid == 0) {
        g_gate[b * 3 + 0] = sigf(d0 + bgate[0]);
        g_gate[b * 3 + 1] = sigf(d1 + bgate[1]);
        g_gate[b * 3 + 2] = sigf(d2 + bgate[2]);
    }
}

// P5b: gate-scaled half rows (scales = gate_flat[l*128 + b], the layer-major quirk)
__device__ void gatescale_row(int b)
{
    const int tid = threadIdx.x;
    const float q0 = g_gate[b], q1 = g_gate[128 + b], q2 = g_gate[256 + b];
    const float* h0 = g_Ht + b * H;
    const float* h1 = g_Ht + (B + b) * H;
    const float* h2 = g_Ht + (2 * B + b) * H;
    for (int h = tid; h < H; h += NT) {
        spl(g_Ah[16] + b * H, g_Ah[17] + b * H, h, q0 * h0[h]);
        spl(g_Ah[18] + b * H, g_Ah[19] + b * H, h, q1 * h1[h]);
        spl(g_Ah[20] + b * H, g_Ah[21] + b * H, h, q2 * h2[h]);
    }
}

__device__ void finalize_row(int b, int t, const float* bout, float* out)
{
    const int tid = threadIdx.x;
    const float gs = g_gate[b] + g_gate[128 + b] + g_gate[256 + b];
    float* o = out + ((size_t)t * B + b) * H;
    for (int h = tid; h < H; h += NT) {
        float s = gs * bout[h];
#pragma unroll
        for (int p = 0; p < 8; p++) s += g_outP[p][b * H + h];
        o[h] = s;
    }
}

// ------------------------- init kernels -------------------------
// transpose + fp16-split repack: src [k][n] fp32 -> g_Whi/g_Wlo [n][k]
__global__ void __launch_bounds__(256)
repack_t(const float* p0, const float* p1, const float* p2, const float* p3,
         const float* p4, const float* p5, const float* p6, const float* p7,
         const float* p8)
{
    __shared__ float tile[32][33];
    const float* srcs[9] = {p0, p1, p2, p3, p4, p5, p6, p7, p8};
    int slab = blockIdx.y;
    const float* src = srcs[slab];
    int ldw   = slab < 6 ? 4097 : (slab == 8 ? 1024 : 4096);
    int ncols = slab == 8 ? 1024 : 4096;
    int ntn = ncols >> 5;
    int bid = blockIdx.x;
    if (bid >= ntn * 32) return;
    int n0 = (bid % ntn) << 5, k0 = (bid / ntn) << 5;
    int lx = threadIdx.x & 31, ly = threadIdx.x >> 5;
    for (int i = 0; i < 32; i += 8)
        tile[ly + i][lx] = src[(size_t)(k0 + ly + i) * ldw + n0 + lx];
    __syncthreads();
    size_t doff = (size_t)slab * SLAB;
    for (int i = 0; i < 32; i += 8) {
        float v = tile[lx][ly + i];
        __half h = __float2half_rn(v);
        size_t di = doff + (size_t)(n0 + ly + i) * 1024 + k0 + lx;
        g_Whi[di] = h;
        g_Wlo[di] = __float2half_rn(v - __half2float(h));
    }
}

__global__ void __launch_bounds__(512)
init_misc(const float* input_,
          const float* Whh0, const float* Wbh0, const float* Wth0,
          const float* Whh1, const float* Wbh1, const float* Wth1)
{
    int idx = blockIdx.x * blockDim.x + threadIdx.x;   // 0 .. 393215
    for (int i = idx; i < 3 * B * H; i += 393216) { g_Ht[i] = 0.f; g_C[i] = 0.f; }
    // zero half buffers 0..15 (h*, zh*, x parities)
    for (int i = idx; i < 16 * B * H; i += 393216) g_Ah[0][i] = __ushort_as_half(0);
    // x step-0 into parity 0 (buffers 12/13)
    if (idx < B * H) spl(g_Ah[12], g_Ah[13], idx, input_[idx]);
    if (idx < 2 * B) g_Z[idx] = 0.f;
    if (idx < H) {
        g_zw[0][idx] = Whh0[(size_t)idx * 4097 + 4096];
        g_zw[1][idx] = Wbh0[(size_t)idx * 4097 + 4096];
        g_zw[2][idx] = Wth0[(size_t)idx * 4097 + 4096];
        g_zw[3][idx] = Whh1[(size_t)idx * 4097 + 4096];
        g_zw[4][idx] = Wbh1[(size_t)idx * 4097 + 4096];
        g_zw[5][idx] = Wth1[(size_t)idx * 4097 + 4096];
    }
    if (idx == 0) { g_count = 0; g_release = 0; }
}

// ------------------------- persistent kernel -------------------------
__global__ void __launch_bounds__(NT, 1)
hm_persist(const float* __restrict__ input_, const int* __restrict__ length,
           const float* __restrict__ b0,   const float* __restrict__ b1,
           const float* __restrict__ b2,   const float* __restrict__ bout,
           const float* __restrict__ Wgate, const float* __restrict__ bgate,
           float* __restrict__ out)
{
    extern __shared__ char smraw[];
    char* sm = (char*)(((ull)smraw + 1023) & ~1023ull);
    const unsigned smb = smem_u32(sm);

    const int bx = blockIdx.x;
    unsigned epoch = 0;

    const size_t S0 = 0, S1 = SLAB, S2 = 2*(size_t)SLAB, S3 = 3*(size_t)SLAB,
                 S4 = 4*(size_t)SLAB, S5 = 5*(size_t)SLAB, S6 = 6*(size_t)SLAB,
                 S7 = 7*(size_t)SLAB, S8 = 8*(size_t)SLAB;

    const int ntB = bx >> 1, ksB = bx & 1;    // N=4096: 64 n-tiles x 2 k-splits
    const int ntO = bx & 15, ksO = bx >> 4;   // N=1024: 16 n-tiles x 8 k-splits

    const float* Ht0 = g_Ht;
    const float* Ht1 = g_Ht + B * H;
    const float* Ht2 = g_Ht + 2 * B * H;
    const float bz0 = b0[4096], bz1 = b1[4096];

    for (int t = 0; t < TSTEPS; t++) {
        const float* xt = input_ + (size_t)t * B * H;
        const int xc = 12 + (t & 1) * 2;           // current x parity buffers
        const int xn = 12 + ((t + 1) & 1) * 2;     // next x parity buffers

        // P1: layer0 GEMM (segs: h0@Whh0, x@Wbh0, (z0old*h1)@Wth0)
        tc_gemm(g_Ah[0], g_Ah[1], g_Ah[xc], g_Ah[xc + 1], g_Ah[8], g_Ah[9],
                S0, S1, S2, ntB * 64, ksB * 24, ksB * 24 + 24,
                g_preP[ksB], 4096, smb);
        if (t > 0) {
            cell_l2(bx, t - 1, b2, length);        // writes h2 + z1old*h2 halves
            finalize_row(bx, t - 1, bout, out);
        }
        gsync(epoch);

        // P2: cell layer0 (z_lm1=1); writes h0 + z0new*h0 halves; converts x[t+1]
        cell_hm(bx, 0, t, xt + bx * H, Ht1 + bx * H,
                g_zw[0], g_zw[1], g_zw[2], bz0, b0, length, 1.0f,
                g_Ah[0], g_Ah[1], g_Ah[6], g_Ah[7],
                (t + 1 < TSTEPS) ? input_ + (size_t)(t + 1) * B * H + bx * H : nullptr,
                (t + 1 < TSTEPS) ? g_Ah[xn] : nullptr, g_Ah[xn + 1]);
        gsync(epoch);

        // P3: layer1 GEMM (h1@Whh1, (z0new*h0)@Wbh1, (z1old*h2)@Wth1)
        tc_gemm(g_Ah[2], g_Ah[3], g_Ah[6], g_Ah[7], g_Ah[10], g_Ah[11],
                S3, S4, S5, ntB * 64, ksB * 24, ksB * 24 + 24,
                g_preP[ksB], 4096, smb);
        gsync(epoch);

        // P4: cell layer1 (z_lm1 = z0 new); writes h1 + z0*h1 halves
        cell_hm(bx, 1, t, Ht0 + bx * H, Ht2 + bx * H,
                g_zw[3], g_zw[4], g_zw[5], bz1, b1, length, g_Z[bx],
                g_Ah[2], g_Ah[3], g_Ah[8], g_Ah[9],
                nullptr, nullptr, nullptr);
        gsync(epoch);

        // P5: layer2 GEMM (h2@Whh2, h1new@Wih2) + gate mixing
        tc_gemm(g_Ah[4], g_Ah[5], g_Ah[2], g_Ah[3], g_Ah[4], g_Ah[5],
                S6, S7, S6, ntB * 64, ksB * 16, ksB * 16 + 16,
                g_pre2P[ksB], 4096, smb);
        gate_row(bx, Wgate, bgate);
        gsync(epoch);

        // P5b: gate-scaled half conversions (needs all gates -> own phase)
        gatescale_row(bx);
        gsync(epoch);

        // P6: gated output mix ((g*h)@Wout x3)
        tc_gemm(g_Ah[16], g_Ah[17], g_Ah[18], g_Ah[19], g_Ah[20], g_Ah[21],
                S8, S8, S8, ntO * 64, ksO * 6, ksO * 6 + 6,
                g_outP[ksO], 1024, smb);
        gsync(epoch);
    }

    cell_l2(bx, TSTEPS - 1, b2, length);
    finalize_row(bx, TSTEPS - 1, bout, out);
}

// ------------------------- host -------------------------
extern "C" void kernel_launch(void* const* d_in, const int* in_sizes, int n_in,
                              void* d_out, int out_size)
{
    const float* input_ = (const float*)d_in[0];
    const int*   length = (const int*)d_in[1];
    const float* Wbh0 = (const float*)d_in[2];
    const float* Whh0 = (const float*)d_in[3];
    const float* Wth0 = (const float*)d_in[4];
    const float* b0   = (const float*)d_in[5];
    const float* Wbh1 = (const float*)d_in[6];
    const float* Whh1 = (const float*)d_in[7];
    const float* Wth1 = (const float*)d_in[8];
    const float* b1   = (const float*)d_in[9];
    const float* Wih2 = (const float*)d_in[10];
    const float* Whh2 = (const float*)d_in[11];
    const float* b2   = (const float*)d_in[12];
    const float* Wout = (const float*)d_in[13];
    const float* bout = (const float*)d_in[14];
    const float* Wgate = (const float*)d_in[15];
    const float* bgate = (const float*)d_in[16];
    float* out = (float*)d_out;

    static int once = 0;
    if (!once) {
        cudaFuncSetAttribute(hm_persist, cudaFuncAttributeMaxDynamicSharedMemorySize,
                             SMEM_BYTES);
        once = 1;
    }

    // slabs: 0..5 HMLSTM (ldw 4097), 6 Whh2, 7 Wih2 (ldw 4096), 8 Wout (ldw 1024)
    repack_t<<<dim3(4096, 9), 256>>>(Whh0, Wbh0, Wth0, Whh1, Wbh1, Wth1,
                                     Whh2, Wih2, Wout);
    init_misc<<<768, 512>>>(input_, Whh0, Wbh0, Wth0, Whh1, Wbh1, Wth1);
    hm_persist<<<NB, NT, SMEM_BYTES>>>(input_, length, b0, b1, b2, bout,
                                       Wgate, bgate, out);
}

// round 15
// speedup vs baseline: 2.8588x; 1.0316x over previous
#include <cuda_runtime.h>
#include <cuda_fp16.h>
#include <math.h>

typedef unsigned long long ull;

#define NB 128
#define NT 512
#define TSTEPS 128
#define B 128
#define H 1024
#define SLAB (4096*1024)

// smem stage layout (bytes from 1024-aligned base): 3 stages of 64 KB
//   +0      A hi  16 KB (128 rows x 128B, SW128-swizzled)
//   +16384  A lo  16 KB
//   +32768  W hi  16 KB (128 rows x 128B)
//   +49152  W lo  16 KB
#define STAGE 65536
#define SMEM_BYTES (3 * STAGE + 1024)

// ------------------------- device state -------------------------
__device__ float g_Ht[3*B*H];
__device__ float g_C [3*B*H];
__device__ float g_Z [2*B];
__device__ float g_preP [4][B*4096];
__device__ float g_pre2P[4][B*4096];
__device__ float g_outP [16][B*H];
__device__ float g_gate[3*B];
__device__ float g_zw[6][H];
// half A-operand buffers, [22][B*H]:
// 0/1 h0 hi/lo   2/3 h1   4/5 h2   6/7 z0*h0   8/9 z0*h1   10/11 z1*h2
// 12/13 x par0   14/15 x par1   16/17 g0*h0   18/19 g1*h1   20/21 g2*h2
__device__ __half g_Ah[22][B*H];
__device__ __half g_Whi[8*SLAB + 1024*1024];   // transposed [n][k] hi halves
__device__ __half g_Wlo[8*SLAB + 1024*1024];   // transposed [n][k] lo halves
__device__ unsigned          g_count;
__device__ volatile unsigned g_release;

__shared__ float s_red[64];

// ------------------------- helpers -------------------------
__device__ __forceinline__ float sigf(float x) { return 1.0f / (1.0f + expf(-x)); }

__device__ __forceinline__ unsigned smem_u32(const void* p) {
    unsigned a;
    asm("{ .reg .u64 t; cvta.to.shared.u64 t, %1; cvt.u32.u64 %0, t; }" : "=r"(a) : "l"(p));
    return a;
}
__device__ __forceinline__ unsigned swz(unsigned off) { return off ^ ((off >> 3) & 0x70); }

__device__ __forceinline__ void cp16(unsigned saddr, const void* g) {
    asm volatile("cp.async.cg.shared.global [%0], [%1], 16;" :: "r"(saddr), "l"(g));
}
#define CP_COMMIT() asm volatile("cp.async.commit_group;" ::: "memory")
#define CP_WAIT0()  asm volatile("cp.async.wait_group 0;" ::: "memory")
#define CP_WAIT1()  asm volatile("cp.async.wait_group 1;" ::: "memory")

__device__ __forceinline__ void ldm4(unsigned* r, unsigned a) {
    asm volatile("ldmatrix.sync.aligned.m8n8.x4.shared.b16 {%0,%1,%2,%3}, [%4];"
                 : "=r"(r[0]), "=r"(r[1]), "=r"(r[2]), "=r"(r[3]) : "r"(a));
}
__device__ __forceinline__ void mma_fp16(float* c, const unsigned* a, const unsigned* b) {
    asm volatile("mma.sync.aligned.m16n8k16.row.col.f32.f16.f16.f32 "
                 "{%0,%1,%2,%3}, {%4,%5,%6,%7}, {%8,%9}, {%0,%1,%2,%3};"
                 : "+f"(c[0]), "+f"(c[1]), "+f"(c[2]), "+f"(c[3])
                 : "r"(a[0]), "r"(a[1]), "r"(a[2]), "r"(a[3]), "r"(b[0]), "r"(b[1]));
}

// exact 2-way fp16 split store
__device__ __forceinline__ void spl(__half* hi, __half* lo, int idx, float v) {
    __half h = __float2half_rn(v);
    hi[idx] = h;
    lo[idx] = __float2half_rn(v - __half2float(h));
}

// ------------------------- grid barrier -------------------------
__device__ __forceinline__ void gsync(unsigned& epoch) {
    __syncthreads();
    if (threadIdx.x == 0) {
        epoch++;
        __threadfence();
        unsigned prev = atomicAdd(&g_count, 1u);
        if (prev == epoch * (unsigned)gridDim.x - 1u) g_release = epoch;
        else while (g_release < epoch) { }
        __threadfence();
    }
    __syncthreads();
}

// ------------------------- HMMA segmented GEMM (CTA 128x128, warp 32x32) ----
// D[0..127][n0..n0+128) = sum over chunks [c0,c1): chunk c: seg=c>>4, kl=(c&15)*64.
// A from precomputed hi/lo half buffers (row-major [B][1024]); W from g_Whi/g_Wlo
// (transposed [n][k]). fp16 split: Ah*Wh + Al*Wh + Ah*Wl, fp32 register accum.
__device__ void tc_gemm(const __half* A0h, const __half* A0l,
                        const __half* A1h, const __half* A1l,
                        const __half* A2h, const __half* A2l,
                        size_t w0, size_t w1, size_t w2,
                        int n0, int c0, int c1,
                        float* outp, int ldo, unsigned smb)
{
    const int tid = threadIdx.x;
    const int wid = tid >> 5, l = tid & 31;
    const int mb = (wid & 3) * 32;      // warp M base (4 warps in M)
    const int nb = (wid >> 2) * 32;     // warp N base (4 warps in N)

    // A x4: lanes 0-15 -> rows mb+(l&15), col blk (l>>4)*16B  (frag pair m16k16)
    const unsigned arow = (unsigned)((mb + (l & 15)) * 128 + ((l >> 4) << 4));
    // B x4: lanes0-7 rows nb+(l&7) k0-7; 8-15 same rows +16B; 16-23 rows+8; 24-31 rows+8,+16
    const unsigned brow = (unsigned)((nb + (l & 7) + ((l & 16) >> 1)) * 128 + ((l & 8) << 1));

    float acc[2][4][4];
#pragma unroll
    for (int i = 0; i < 2; i++)
#pragma unroll
        for (int j = 0; j < 4; j++)
#pragma unroll
            for (int q = 0; q < 4; q++) acc[i][j][q] = 0.0f;

    auto issue = [&](int c, int s) {
        const int seg = c >> 4;
        const int kl  = (c & 15) << 6;
        const __half* Ah = seg == 0 ? A0h : (seg == 1 ? A1h : A2h);
        const __half* Al = seg == 0 ? A0l : (seg == 1 ? A1l : A2l);
        const size_t  wo = seg == 0 ? w0 : (seg == 1 ? w1 : w2);
        const unsigned sb = smb + (unsigned)(s * STAGE);
#pragma unroll
        for (int p = 0; p < 2; p++) {          // A: 128 rows x 64 halves, hi+lo
            int idx = tid + (p << 9);
            int row = idx >> 3, cc = idx & 7;
            unsigned d = sb + swz((unsigned)(row * 128 + cc * 16));
            size_t go = (size_t)row * 1024 + kl + cc * 8;
            cp16(d, Ah + go);
            cp16(d + 16384, Al + go);
        }
#pragma unroll
        for (int p = 0; p < 2; p++) {          // W: 128 rows x 64 halves, hi+lo
            int idx = tid + (p << 9);
            int row = idx >> 3, cc = idx & 7;
            unsigned d = sb + 32768 + swz((unsigned)(row * 128 + cc * 16));
            size_t go = wo + (size_t)(n0 + row) * 1024 + kl + cc * 8;
            cp16(d, g_Whi + go);
            cp16(d + 16384, g_Wlo + go);
        }
        CP_COMMIT();
    };

    auto compute = [&](int s) {
        const unsigned sb = smb + (unsigned)(s * STAGE);
#pragma unroll
        for (int ks = 0; ks < 4; ks++) {
            const unsigned ca = (unsigned)(ks * 32);
            unsigned ah0[4], ah1[4], al0[4], al1[4];
            unsigned bh0[4], bh1[4], bl0[4], bl1[4];
            ldm4(ah0, sb + swz(arow + ca));
            ldm4(ah1, sb + swz(arow + 2048 + ca));
            ldm4(al0, sb + 16384 + swz(arow + ca));
            ldm4(al1, sb + 16384 + swz(arow + 2048 + ca));
            ldm4(bh0, sb + 32768 + swz(brow + ca));          // n-frags nb+0..15
            ldm4(bh1, sb + 32768 + swz(brow + 2048 + ca));   // n-frags nb+16..31
            ldm4(bl0, sb + 49152 + swz(brow + ca));
            ldm4(bl1, sb + 49152 + swz(brow + 2048 + ca));
            // hi*hi
            mma_fp16(acc[0][0], ah0, bh0);     mma_fp16(acc[0][1], ah0, bh0 + 2);
            mma_fp16(acc[0][2], ah0, bh1);     mma_fp16(acc[0][3], ah0, bh1 + 2);
            mma_fp16(acc[1][0], ah1, bh0);     mma_fp16(acc[1][1], ah1, bh0 + 2);
            mma_fp16(acc[1][2], ah1, bh1);     mma_fp16(acc[1][3], ah1, bh1 + 2);
            // lo*hi
            mma_fp16(acc[0][0], al0, bh0);     mma_fp16(acc[0][1], al0, bh0 + 2);
            mma_fp16(acc[0][2], al0, bh1);     mma_fp16(acc[0][3], al0, bh1 + 2);
            mma_fp16(acc[1][0], al1, bh0);     mma_fp16(acc[1][1], al1, bh0 + 2);
            mma_fp16(acc[1][2], al1, bh1);     mma_fp16(acc[1][3], al1, bh1 + 2);
            // hi*lo
            mma_fp16(acc[0][0], ah0, bl0);     mma_fp16(acc[0][1], ah0, bl0 + 2);
            mma_fp16(acc[0][2], ah0, bl1);     mma_fp16(acc[0][3], ah0, bl1 + 2);
            mma_fp16(acc[1][0], ah1, bl0);     mma_fp16(acc[1][1], ah1, bl0 + 2);
            mma_fp16(acc[1][2], ah1, bl1);     mma_fp16(acc[1][3], ah1, bl1 + 2);
        }
    };

    issue(c0, 0);
    for (int c = c0; c < c1; c++) {
        int s = (c - c0) % 3;
        if (c + 1 < c1) { issue(c + 1, (s + 1) % 3); CP_WAIT1(); }
        else            { CP_WAIT0(); }
        __syncthreads();
        compute(s);
    }

    // epilogue: frag regs 0,1 -> (row, col..col+1); 2,3 -> row+8
#pragma unroll
    for (int fm = 0; fm < 2; fm++)
#pragma unroll
        for (int j = 0; j < 4; j++) {
            int r0 = mb + fm * 16 + (l >> 2);
            int cc = n0 + nb + j * 8 + (l & 3) * 2;
            float* o = outp + (size_t)r0 * ldo + cc;
            *reinterpret_cast<float2*>(o) = make_float2(acc[fm][j][0], acc[fm][j][1]);
            float* o2 = outp + (size_t)(r0 + 8) * ldo + cc;
            *reinterpret_cast<float2*>(o2) = make_float2(acc[fm][j][2], acc[fm][j][3]);
        }
}

// ------------------------- reductions -------------------------
__device__ __forceinline__ float wred(float v) {
    v += __shfl_xor_sync(0xffffffffu, v, 16);
    v += __shfl_xor_sync(0xffffffffu, v, 8);
    v += __shfl_xor_sync(0xffffffffu, v, 4);
    v += __shfl_xor_sync(0xffffffffu, v, 2);
    v += __shfl_xor_sync(0xffffffffu, v, 1);
    return v;
}
__device__ void red3(float s0, float s1, float s2, float& r0, float& r1, float& r2)
{
    s0 = wred(s0); s1 = wred(s1); s2 = wred(s2);
    const int w = threadIdx.x >> 5, lane = threadIdx.x & 31;
    if (lane == 0) { s_red[w] = s0; s_red[16 + w] = s1; s_red[32 + w] = s2; }
    __syncthreads();
    if (threadIdx.x < 3) {
        float v = 0.f;
#pragma unroll
        for (int i = 0; i < 16; i++) v += s_red[threadIdx.x * 16 + i];
        s_red[48 + threadIdx.x] = v;
    }
    __syncthreads();
    r0 = s_red[48]; r1 = s_red[49]; r2 = s_red[50];
    __syncthreads();
}

// ------------------------- cells (one CTA = one batch row) -------------------------
__device__ void cell_hm(int b, int lyr, int t,
                        const float* xb, const float* xtop,
                        const float* zw_hh, const float* zw_bh, const float* zw_th,
                        float bz, const float* bias, const int* length, float z_lm1,
                        __half* hhi, __half* hlo, __half* zhhi, __half* zhlo,
                        const float* xnext, __half* xnhi, __half* xnlo)
{
    const int tid = threadIdx.x;
    float* hrow = g_Ht + (lyr * B + b) * H;
    float* crow = g_C  + (lyr * B + b) * H;
    const float z_tm1 = g_Z[lyr * B + b];

    float s0 = 0.f, s1 = 0.f, s2 = 0.f;
    for (int k = tid; k < H; k += NT) {
        s0 += hrow[k] * zw_hh[k];
        s1 += xb[k]   * zw_bh[k];
        s2 += xtop[k] * zw_th[k];
    }
    float d0, d1, d2;
    red3(s0, s1, s2, d0, d1, d2);
    const float prez = d0 + bz + z_lm1 * d1 + z_tm1 * d2;
    const float znew = (prez > 0.0f) ? 1.0f : 0.0f;   // round-half-even == (z>0)
    if (tid == 0) g_Z[lyr * B + b] = znew;
    const float zs = (lyr == 0) ? znew : z_lm1;

    const float tm   = (t < length[b]) ? 1.0f : 0.0f;
    const float keep = 1.0f - z_tm1;
    const float cp   = (1.0f - z_tm1) * (1.0f - z_lm1);
    const float* P0 = g_preP[0] + b * 4096;
    const float* P1 = g_preP[1] + b * 4096;
    const float* P2 = g_preP[2] + b * 4096;
    const float* P3 = g_preP[3] + b * 4096;

    for (int h = tid; h < H; h += NT) {
        float f = P0[h]        + P1[h]        + P2[h]        + P3[h]        + bias[h];
        float i = P0[1024 + h] + P1[1024 + h] + P2[1024 + h] + P3[1024 + h] + bias[1024 + h];
        float o = P0[2048 + h] + P1[2048 + h] + P2[2048 + h] + P3[2048 + h] + bias[2048 + h];
        float g = P0[3072 + h] + P1[3072 + h] + P2[3072 + h] + P3[3072 + h] + bias[3072 + h];
        float c_old = crow[h], h_old = hrow[h];
        float c1 = keep * sigf(f) * c_old + sigf(i) * tanhf(g);
        float h1 = sigf(o) * tanhf(c1);
        float hn = cp * h_old + (1.0f - cp) * h1;
        float cn = cp * c_old + (1.0f - cp) * c1;
        hn = tm * hn + (1.0f - tm) * h_old;
        cn = tm * cn + (1.0f - tm) * c_old;
        hrow[h] = hn;
        crow[h] = cn;
        spl(hhi + b * H, hlo + b * H, h, hn);
        spl(zhhi + b * H, zhlo + b * H, h, zs * hn);
        if (xnhi) spl(xnhi + b * H, xnlo + b * H, h, xnext[h]);
    }
}

__device__ void cell_l2(int b, int t, const float* bias, const int* length)
{
    const int tid = threadIdx.x;
    float* hrow = g_Ht + (2 * B + b) * H;
    float* crow = g_C  + (2 * B + b) * H;
    const float cp = 1.0f - g_Z[b];
    const float tm = (t < length[b]) ? 1.0f : 0.0f;
    const float zs = g_Z[B + b];            // z1_old for the upcoming step's P3
    const float* P0 = g_pre2P[0] + b * 4096;
    const float* P1 = g_pre2P[1] + b * 4096;
    const float* P2 = g_pre2P[2] + b * 4096;
    const float* P3 = g_pre2P[3] + b * 4096;

    for (int h = tid; h < H; h += NT) {
        float f = P0[h]        + P1[h]        + P2[h]        + P3[h]        + bias[h];
        float i = P0[1024 + h] + P1[1024 + h] + P2[1024 + h] + P3[1024 + h] + bias[1024 + h];
        float o = P0[2048 + h] + P1[2048 + h] + P2[2048 + h] + P3[2048 + h] + bias[2048 + h];
        float g = P0[3072 + h] + P1[3072 + h] + P2[3072 + h] + P3[3072 + h] + bias[3072 + h];
        float c_old = crow[h], h_old = hrow[h];
        float c1 = sigf(f) * c_old + sigf(i) * tanhf(g);
        float h1 = sigf(o) * tanhf(c1);
        float hn = cp * h_old + (1.0f - cp) * h1;
        float cn = cp * c_old + (1.0f - cp) * c1;
        hn = tm * hn + (1.0f - tm) * h_old;
        cn = tm * cn + (1.0f - tm) * c_old;
        hrow[h] = hn;
        crow[h] = cn;
        spl(g_Ah[4] + b * H, g_Ah[5] + b * H, h, hn);
        spl(g_Ah[10] + b * H, g_Ah[11] + b * H, h, zs * hn);
    }
}

__device__ void gate_row(int b, const float* Wgate, const float* bgate)
{
    const int tid = threadIdx.x;
    float s0 = 0.f, s1 = 0.f, s2 = 0.f;
    const float* hb = g_Ht + b * 3072;      // flat Ht.reshape(B, L*H) row b
    for (int j = tid; j < 3072; j += NT) {
        float h = hb[j];
        s0 += h * Wgate[j * 3 + 0];
        s1 += h * Wgate[j * 3 + 1];
        s2 += h * Wgate[j * 3 + 2];
    }
    float d0, d1, d2;
    red3(s0, s1, s2, d0, d1, d2);
    if (tid == 0) {
        g_gate[b * 3 + 0] = sigf(d0 + bgate[0]);
        g_gate[b * 3 + 1] = sigf(d1 + bgate[1]);
        g_gate[b * 3 + 2] = sigf(d2 + bgate[2]);
    }
}

// gate-scaled half rows (scales = gate_flat[l*128 + b], the layer-major quirk)
__device__ void gatescale_row(int b)
{
    const int tid = threadIdx.x;
    const float q0 = g_gate[b], q1 = g_gate[128 + b], q2 = g_gate[256 + b];
    const float* h0 = g_Ht + b * H;
    const float* h1 = g_Ht + (B + b) * H;
    const float* h2 = g_Ht + (2 * B + b) * H;
    for (int h = tid; h < H; h += NT) {
        spl(g_Ah[16] + b * H, g_Ah[17] + b * H, h, q0 * h0[h]);
        spl(g_Ah[18] + b * H, g_Ah[19] + b * H, h, q1 * h1[h]);
        spl(g_Ah[20] + b * H, g_Ah[21] + b * H, h, q2 * h2[h]);
    }
}

__device__ void finalize_row(int b, int t, const float* bout, float* out)
{
    const int tid = threadIdx.x;
    const float gs = g_gate[b] + g_gate[128 + b] + g_gate[256 + b];
    float* o = out + ((size_t)t * B + b) * H;
    for (int h = tid; h < H; h += NT) {
        float s = gs * bout[h];
#pragma unroll
        for (int p = 0; p < 16; p++) s += g_outP[p][b * H + h];
        o[h] = s;
    }
}

// ------------------------- init kernels -------------------------
__global__ void __launch_bounds__(256)
repack_t(const float* p0, const float* p1, const float* p2, const float* p3,
         const float* p4, const float* p5, const float* p6, const float* p7,
         const float* p8)
{
    __shared__ float tile[32][33];
    const float* srcs[9] = {p0, p1, p2, p3, p4, p5, p6, p7, p8};
    int slab = blockIdx.y;
    const float* src = srcs[slab];
    int ldw   = slab < 6 ? 4097 : (slab == 8 ? 1024 : 4096);
    int ncols = slab == 8 ? 1024 : 4096;
    int ntn = ncols >> 5;
    int bid = blockIdx.x;
    if (bid >= ntn * 32) return;
    int n0 = (bid % ntn) << 5, k0 = (bid / ntn) << 5;
    int lx = threadIdx.x & 31, ly = threadIdx.x >> 5;
    for (int i = 0; i < 32; i += 8)
        tile[ly + i][lx] = src[(size_t)(k0 + ly + i) * ldw + n0 + lx];
    __syncthreads();
    size_t doff = (size_t)slab * SLAB;
    for (int i = 0; i < 32; i += 8) {
        float v = tile[lx][ly + i];
        __half h = __float2half_rn(v);
        size_t di = doff + (size_t)(n0 + ly + i) * 1024 + k0 + lx;
        g_Whi[di] = h;
        g_Wlo[di] = __float2half_rn(v - __half2float(h));
    }
}

__global__ void __launch_bounds__(512)
init_misc(const float* input_,
          const float* Whh0, const float* Wbh0, const float* Wth0,
          const float* Whh1, const float* Wbh1, const float* Wth1)
{
    int idx = blockIdx.x * blockDim.x + threadIdx.x;   // 0 .. 393215
    for (int i = idx; i < 3 * B * H; i += 393216) { g_Ht[i] = 0.f; g_C[i] = 0.f; }
    for (int i = idx; i < 16 * B * H; i += 393216) g_Ah[0][i] = __ushort_as_half(0);
    if (idx < B * H) spl(g_Ah[12], g_Ah[13], idx, input_[idx]);
    if (idx < 2 * B) g_Z[idx] = 0.f;
    if (idx < H) {
        g_zw[0][idx] = Whh0[(size_t)idx * 4097 + 4096];
        g_zw[1][idx] = Wbh0[(size_t)idx * 4097 + 4096];
        g_zw[2][idx] = Wth0[(size_t)idx * 4097 + 4096];
        g_zw[3][idx] = Whh1[(size_t)idx * 4097 + 4096];
        g_zw[4][idx] = Wbh1[(size_t)idx * 4097 + 4096];
        g_zw[5][idx] = Wth1[(size_t)idx * 4097 + 4096];
    }
    if (idx == 0) { g_count = 0; g_release = 0; }
}

// ------------------------- persistent kernel -------------------------
__global__ void __launch_bounds__(NT, 1)
hm_persist(const float* __restrict__ input_, const int* __restrict__ length,
           const float* __restrict__ b0,   const float* __restrict__ b1,
           const float* __restrict__ b2,   const float* __restrict__ bout,
           const float* __restrict__ Wgate, const float* __restrict__ bgate,
           float* __restrict__ out)
{
    extern __shared__ char smraw[];
    char* sm = (char*)(((ull)smraw + 1023) & ~1023ull);
    const unsigned smb = smem_u32(sm);

    const int bx = blockIdx.x;
    unsigned epoch = 0;

    const size_t S0 = 0, S1 = SLAB, S2 = 2*(size_t)SLAB, S3 = 3*(size_t)SLAB,
                 S4 = 4*(size_t)SLAB, S5 = 5*(size_t)SLAB, S6 = 6*(size_t)SLAB,
                 S7 = 7*(size_t)SLAB, S8 = 8*(size_t)SLAB;

    const int ntB = bx >> 2, ksB = bx & 3;    // N=4096: 32 n-tiles x 4 k-splits
    const int ntO = bx & 7,  ksO = bx >> 3;   // N=1024: 8 n-tiles x 16 k-splits

    const float* Ht1 = g_Ht + B * H;
    const float* Ht2 = g_Ht + 2 * B * H;
    const float* Ht0 = g_Ht;
    const float bz0 = b0[4096], bz1 = b1[4096];

    for (int t = 0; t < TSTEPS; t++) {
        const float* xt = input_ + (size_t)t * B * H;
        const int xc = 12 + (t & 1) * 2;           // current x parity buffers
        const int xn = 12 + ((t + 1) & 1) * 2;     // next x parity buffers

        // P1: layer0 GEMM (segs: h0@Whh0, x@Wbh0, (z0old*h1)@Wth0)
        tc_gemm(g_Ah[0], g_Ah[1], g_Ah[xc], g_Ah[xc + 1], g_Ah[8], g_Ah[9],
                S0, S1, S2, ntB * 128, ksB * 12, ksB * 12 + 12,
                g_preP[ksB], 4096, smb);
        if (t > 0) {
            cell_l2(bx, t - 1, b2, length);        // writes h2 + z1old*h2 halves
            finalize_row(bx, t - 1, bout, out);
        }
        gsync(epoch);

        // P2: cell layer0 (z_lm1=1); writes h0 + z0new*h0 halves; converts x[t+1]
        cell_hm(bx, 0, t, xt + bx * H, Ht1 + bx * H,
                g_zw[0], g_zw[1], g_zw[2], bz0, b0, length, 1.0f,
                g_Ah[0], g_Ah[1], g_Ah[6], g_Ah[7],
                (t + 1 < TSTEPS) ? input_ + (size_t)(t + 1) * B * H + bx * H : nullptr,
                (t + 1 < TSTEPS) ? g_Ah[xn] : nullptr, g_Ah[xn + 1]);
        gsync(epoch);

        // P3: layer1 GEMM (h1@Whh1, (z0new*h0)@Wbh1, (z1old*h2)@Wth1)
        tc_gemm(g_Ah[2], g_Ah[3], g_Ah[6], g_Ah[7], g_Ah[10], g_Ah[11],
                S3, S4, S5, ntB * 128, ksB * 12, ksB * 12 + 12,
                g_preP[ksB], 4096, smb);
        gsync(epoch);

        // P4: cell layer1 (z_lm1 = z0 new); writes h1 + z0*h1 halves
        cell_hm(bx, 1, t, Ht0 + bx * H, Ht2 + bx * H,
                g_zw[3], g_zw[4], g_zw[5], bz1, b1, length, g_Z[bx],
                g_Ah[2], g_Ah[3], g_Ah[8], g_Ah[9],
                nullptr, nullptr, nullptr);
        gsync(epoch);

        // P5: layer2 GEMM (h2@Whh2, h1new@Wih2) + gate mixing
        tc_gemm(g_Ah[4], g_Ah[5], g_Ah[2], g_Ah[3], g_Ah[4], g_Ah[5],
                S6, S7, S6, ntB * 128, ksB * 8, ksB * 8 + 8,
                g_pre2P[ksB], 4096, smb);
        gate_row(bx, Wgate, bgate);
        gsync(epoch);

        // P5b: gate-scaled half conversions (needs all gates -> own phase)
        gatescale_row(bx);
        gsync(epoch);

        // P6: gated output mix ((g*h)@Wout x3)
        tc_gemm(g_Ah[16], g_Ah[17], g_Ah[18], g_Ah[19], g_Ah[20], g_Ah[21],
                S8, S8, S8, ntO * 128, ksO * 3, ksO * 3 + 3,
                g_outP[ksO], 1024, smb);
        gsync(epoch);
    }

    cell_l2(bx, TSTEPS - 1, b2, length);
    finalize_row(bx, TSTEPS - 1, bout, out);
}

// ------------------------- host -------------------------
extern "C" void kernel_launch(void* const* d_in, const int* in_sizes, int n_in,
                              void* d_out, int out_size)
{
    const float* input_ = (const float*)d_in[0];
    const int*   length = (const int*)d_in[1];
    const float* Wbh0 = (const float*)d_in[2];
    const float* Whh0 = (const float*)d_in[3];
    const float* Wth0 = (const float*)d_in[4];
    const float* b0   = (const float*)d_in[5];
    const float* Wbh1 = (const float*)d_in[6];
    const float* Whh1 = (const float*)d_in[7];
    const float* Wth1 = (const float*)d_in[8];
    const float* b1   = (const float*)d_in[9];
    const float* Wih2 = (const float*)d_in[10];
    const float* Whh2 = (const float*)d_in[11];
    const float* b2   = (const float*)d_in[12];
    const float* Wout = (const float*)d_in[13];
    const float* bout = (const float*)d_in[14];
    const float* Wgate = (const float*)d_in[15];
    const float* bgate = (const float*)d_in[16];
    float* out = (float*)d_out;

    static int once = 0;
    if (!once) {
        cudaFuncSetAttribute(hm_persist, cudaFuncAttributeMaxDynamicSharedMemorySize,
                             SMEM_BYTES);
        once = 1;
    }

    // slabs: 0..5 HMLSTM (ldw 4097), 6 Whh2, 7 Wih2 (ldw 4096), 8 Wout (ldw 1024)
    repack_t<<<dim3(4096, 9), 256>>>(Whh0, Wbh0, Wth0, Whh1, Wbh1, Wth1,
                                     Whh2, Wih2, Wout);
    init_misc<<<768, 512>>>(input_, Whh0, Wbh0, Wth0, Whh1, Wbh1, Wth1);
    hm_persist<<<NB, NT, SMEM_BYTES>>>(input_, length, b0, b1, b2, bout,
                                       Wgate, bgate, out);
}

// round 16
// speedup vs baseline: 3.0534x; 1.0681x over previous
#include <cuda_runtime.h>
#include <cuda_fp16.h>
#include <math.h>

typedef unsigned long long ull;

#define NB 128
#define NT 512
#define TSTEPS 128
#define B 128
#define H 1024
#define SLAB (4096*1024)      // halves per big weight slab

// smem stage: 64 KB = A hi 16K | A lo 16K | W hi 16K | W lo 16K ; 3 stages
#define STAGE 65536
#define SMEM_BYTES (3 * STAGE + 1024)

// ------------------------- device state -------------------------
__device__ float g_Ht[3*B*H];
__device__ float g_C [3*B*H];
__device__ float g_Z [2*B];
__device__ float g_preP [4][B*4096];
__device__ float g_pre2P[4][B*4096];
__device__ float g_outP [12][B*H];      // P6: 12 seg-aligned k-splits
__device__ float g_gate[3*B];
__device__ float g_zw[6][H];
// half A buffers, tiled-swizzled layout: [chunk(16)][tile 8192 halves]
// 0/1 h0 hi/lo  2/3 h1  4/5 h2  6/7 z0*h0  8/9 z0*h1  10/11 z1*h2  12/13 x p0  14/15 x p1
__device__ __align__(16) __half g_Ah[16][B*H];
__device__ __align__(16) __half g_Whi[8*SLAB + 1024*1024];  // tiled [ntile][chunk][8192]
__device__ __align__(16) __half g_Wlo[8*SLAB + 1024*1024];
__device__ unsigned          g_count;
__device__ volatile unsigned g_release;

__shared__ float s_red[64];
__shared__ ull   s_mb[3];

// ------------------------- helpers -------------------------
__device__ __forceinline__ float sigf(float x) { return 1.0f / (1.0f + expf(-x)); }

__device__ __forceinline__ unsigned smem_u32(const void* p) {
    unsigned a;
    asm("{ .reg .u64 t; cvta.to.shared.u64 t, %1; cvt.u32.u64 %0, t; }" : "=r"(a) : "l"(p));
    return a;
}
__device__ __forceinline__ unsigned swz(unsigned off) { return off ^ ((off >> 3) & 0x70); }

__device__ __forceinline__ void bulk_cp(unsigned dst, const void* src, unsigned bytes,
                                        unsigned mbar) {
    asm volatile("cp.async.bulk.shared::cluster.global.mbarrier::complete_tx::bytes "
                 "[%0], [%1], %2, [%3];"
                 :: "r"(dst), "l"(src), "r"(bytes), "r"(mbar) : "memory");
}
__device__ __forceinline__ void mb_expect(unsigned mbar, unsigned tx) {
    asm volatile("mbarrier.arrive.expect_tx.shared.b64 _, [%0], %1;"
                 :: "r"(mbar), "r"(tx) : "memory");
}
__device__ __forceinline__ void mb_wait(unsigned mbar, unsigned par) {
    unsigned done;
    asm volatile(
        "{\n\t.reg .pred p;\n\t"
        "mbarrier.try_wait.parity.acquire.cta.shared::cta.b64 p, [%1], %2;\n\t"
        "selp.b32 %0, 1, 0, p;\n\t}" : "=r"(done) : "r"(mbar), "r"(par) : "memory");
    while (!done) {
        asm volatile(
            "{\n\t.reg .pred p;\n\t"
            "mbarrier.try_wait.parity.acquire.cta.shared::cta.b64 p, [%1], %2, 0x989680;\n\t"
            "selp.b32 %0, 1, 0, p;\n\t}" : "=r"(done) : "r"(mbar), "r"(par) : "memory");
    }
}

__device__ __forceinline__ void ldm4(unsigned* r, unsigned a) {
    asm volatile("ldmatrix.sync.aligned.m8n8.x4.shared.b16 {%0,%1,%2,%3}, [%4];"
                 : "=r"(r[0]), "=r"(r[1]), "=r"(r[2]), "=r"(r[3]) : "r"(a));
}
__device__ __forceinline__ void mma_fp16(float* c, const unsigned* a, const unsigned* b) {
    asm volatile("mma.sync.aligned.m16n8k16.row.col.f32.f16.f16.f32 "
                 "{%0,%1,%2,%3}, {%4,%5,%6,%7}, {%8,%9}, {%0,%1,%2,%3};"
                 : "+f"(c[0]), "+f"(c[1]), "+f"(c[2]), "+f"(c[3])
                 : "r"(a[0]), "r"(a[1]), "r"(a[2]), "r"(a[3]), "r"(b[0]), "r"(b[1]));
}

// exact fp16 split store into tiled-swizzled A buffer (row b, element h)
__device__ __forceinline__ void spl_t(__half* hi, __half* lo, int b, int h, float v) {
    int off = ((h >> 6) << 13) + (b << 6) + ((((h >> 3) & 7) ^ (b & 7)) << 3) + (h & 7);
    __half hh = __float2half_rn(v);
    hi[off] = hh;
    lo[off] = __float2half_rn(v - __half2float(hh));
}

// ------------------------- grid barrier -------------------------
__device__ __forceinline__ void gsync(unsigned& epoch) {
    __syncthreads();
    if (threadIdx.x == 0) {
        epoch++;
        __threadfence();
        unsigned prev = atomicAdd(&g_count, 1u);
        if (prev == epoch * (unsigned)gridDim.x - 1u) g_release = epoch;
        else while (g_release < epoch) { }
        __threadfence();
    }
    __syncthreads();
}

// ------------------------- HMMA segmented GEMM (CTA 128x128, warp 32x32) ----
// chunk c: seg = c>>4, local chunk = c&15 (K=64 halves). Tiles are 16KB
// pre-swizzled blocks; loaded whole via cp.async.bulk.
__device__ void tc_gemm(const __half* A0h, const __half* A0l,
                        const __half* A1h, const __half* A1l,
                        const __half* A2h, const __half* A2l,
                        size_t w0, size_t w1, size_t w2,
                        int n0, int c0, int c1,
                        float* outp, int ldo, unsigned smb, int* par)
{
    const int tid = threadIdx.x;
    const int wid = tid >> 5, l = tid & 31;
    const int mb = (wid & 3) * 32;
    const int nb = (wid >> 2) * 32;
    const int ntile = n0 >> 7;

    const unsigned arow = (unsigned)((mb + (l & 15)) * 128 + ((l >> 4) << 4));
    const unsigned brow = (unsigned)((nb + (l & 7) + ((l & 16) >> 1)) * 128 + ((l & 8) << 1));

    float acc[2][4][4];
#pragma unroll
    for (int i = 0; i < 2; i++)
#pragma unroll
        for (int j = 0; j < 4; j++)
#pragma unroll
            for (int q = 0; q < 4; q++) acc[i][j][q] = 0.0f;

    auto issue = [&](int c, int s) {
        if (tid == 0) {
            const int seg = c >> 4, lc = c & 15;
            const __half* Ah = seg == 0 ? A0h : (seg == 1 ? A1h : A2h);
            const __half* Al = seg == 0 ? A0l : (seg == 1 ? A1l : A2l);
            const size_t  wt = (seg == 0 ? w0 : (seg == 1 ? w1 : w2))
                             + ((size_t)ntile * 16 + lc) * 8192;
            const unsigned sb = smb + (unsigned)(s * STAGE);
            const unsigned mbar = smem_u32(&s_mb[s]);
            asm volatile("fence.proxy.async.shared::cta;" ::: "memory");
            mb_expect(mbar, 65536u);
            bulk_cp(sb,         Ah + (size_t)lc * 8192, 16384u, mbar);
            bulk_cp(sb + 16384, Al + (size_t)lc * 8192, 16384u, mbar);
            bulk_cp(sb + 32768, g_Whi + wt,             16384u, mbar);
            bulk_cp(sb + 49152, g_Wlo + wt,             16384u, mbar);
        }
    };

    auto compute = [&](int s) {
        const unsigned sb = smb + (unsigned)(s * STAGE);
#pragma unroll
        for (int ks = 0; ks < 4; ks++) {
            const unsigned ca = (unsigned)(ks * 32);
            unsigned ah0[4], ah1[4], al0[4], al1[4];
            unsigned bh0[4], bh1[4], bl0[4], bl1[4];
            ldm4(ah0, sb + swz(arow + ca));
            ldm4(ah1, sb + swz(arow + 2048 + ca));
            ldm4(al0, sb + 16384 + swz(arow + ca));
            ldm4(al1, sb + 16384 + swz(arow + 2048 + ca));
            ldm4(bh0, sb + 32768 + swz(brow + ca));
            ldm4(bh1, sb + 32768 + swz(brow + 2048 + ca));
            ldm4(bl0, sb + 49152 + swz(brow + ca));
            ldm4(bl1, sb + 49152 + swz(brow + 2048 + ca));
            mma_fp16(acc[0][0], ah0, bh0);     mma_fp16(acc[0][1], ah0, bh0 + 2);
            mma_fp16(acc[0][2], ah0, bh1);     mma_fp16(acc[0][3], ah0, bh1 + 2);
            mma_fp16(acc[1][0], ah1, bh0);     mma_fp16(acc[1][1], ah1, bh0 + 2);
            mma_fp16(acc[1][2], ah1, bh1);     mma_fp16(acc[1][3], ah1, bh1 + 2);
            mma_fp16(acc[0][0], al0, bh0);     mma_fp16(acc[0][1], al0, bh0 + 2);
            mma_fp16(acc[0][2], al0, bh1);     mma_fp16(acc[0][3], al0, bh1 + 2);
            mma_fp16(acc[1][0], al1, bh0);     mma_fp16(acc[1][1], al1, bh0 + 2);
            mma_fp16(acc[1][2], al1, bh1);     mma_fp16(acc[1][3], al1, bh1 + 2);
            mma_fp16(acc[0][0], ah0, bl0);     mma_fp16(acc[0][1], ah0, bl0 + 2);
            mma_fp16(acc[0][2], ah0, bl1);     mma_fp16(acc[0][3], ah0, bl1 + 2);
            mma_fp16(acc[1][0], ah1, bl0);     mma_fp16(acc[1][1], ah1, bl0 + 2);
            mma_fp16(acc[1][2], ah1, bl1);     mma_fp16(acc[1][3], ah1, bl1 + 2);
        }
    };

    issue(c0, 0);
    if (c0 + 1 < c1) issue(c0 + 1, 1);
    for (int c = c0; c < c1; c++) {
        int s = (c - c0) % 3;
        if (c + 2 < c1) { __syncthreads(); issue(c + 2, (s + 2) % 3); }
        mb_wait(smem_u32(&s_mb[s]), (unsigned)par[s]);
        par[s] ^= 1;
        compute(s);
    }

#pragma unroll
    for (int fm = 0; fm < 2; fm++)
#pragma unroll
        for (int j = 0; j < 4; j++) {
            int r0 = mb + fm * 16 + (l >> 2);
            int cc = n0 + nb + j * 8 + (l & 3) * 2;
            float* o = outp + (size_t)r0 * ldo + cc;
            *reinterpret_cast<float2*>(o) = make_float2(acc[fm][j][0], acc[fm][j][1]);
            float* o2 = outp + (size_t)(r0 + 8) * ldo + cc;
            *reinterpret_cast<float2*>(o2) = make_float2(acc[fm][j][2], acc[fm][j][3]);
        }
}

// ------------------------- reductions -------------------------
__device__ __forceinline__ float wred(float v) {
    v += __shfl_xor_sync(0xffffffffu, v, 16);
    v += __shfl_xor_sync(0xffffffffu, v, 8);
    v += __shfl_xor_sync(0xffffffffu, v, 4);
    v += __shfl_xor_sync(0xffffffffu, v, 2);
    v += __shfl_xor_sync(0xffffffffu, v, 1);
    return v;
}
__device__ void red3(float s0, float s1, float s2, float& r0, float& r1, float& r2)
{
    s0 = wred(s0); s1 = wred(s1); s2 = wred(s2);
    const int w = threadIdx.x >> 5, lane = threadIdx.x & 31;
    if (lane == 0) { s_red[w] = s0; s_red[16 + w] = s1; s_red[32 + w] = s2; }
    __syncthreads();
    if (threadIdx.x < 3) {
        float v = 0.f;
#pragma unroll
        for (int i = 0; i < 16; i++) v += s_red[threadIdx.x * 16 + i];
        s_red[48 + threadIdx.x] = v;
    }
    __syncthreads();
    r0 = s_red[48]; r1 = s_red[49]; r2 = s_red[50];
    __syncthreads();
}

// ------------------------- cells (one CTA = one batch row) -------------------------
__device__ void cell_hm(int b, int lyr, int t,
                        const float* xb, const float* xtop,
                        const float* zw_hh, const float* zw_bh, const float* zw_th,
                        float bz, const float* bias, const int* length, float z_lm1,
                        __half* hhi, __half* hlo, __half* zhhi, __half* zhlo,
                        const float* xnext, __half* xnhi, __half* xnlo)
{
    const int tid = threadIdx.x;
    float* hrow = g_Ht + (lyr * B + b) * H;
    float* crow = g_C  + (lyr * B + b) * H;
    const float z_tm1 = g_Z[lyr * B + b];

    float s0 = 0.f, s1 = 0.f, s2 = 0.f;
    for (int k = tid; k < H; k += NT) {
        s0 += hrow[k] * zw_hh[k];
        s1 += xb[k]   * zw_bh[k];
        s2 += xtop[k] * zw_th[k];
    }
    float d0, d1, d2;
    red3(s0, s1, s2, d0, d1, d2);
    const float prez = d0 + bz + z_lm1 * d1 + z_tm1 * d2;
    const float znew = (prez > 0.0f) ? 1.0f : 0.0f;   // round-half-even == (z>0)
    if (tid == 0) g_Z[lyr * B + b] = znew;
    const float zs = (lyr == 0) ? znew : z_lm1;

    const float tm   = (t < length[b]) ? 1.0f : 0.0f;
    const float keep = 1.0f - z_tm1;
    const float cp   = (1.0f - z_tm1) * (1.0f - z_lm1);
    const float* P0 = g_preP[0] + b * 4096;
    const float* P1 = g_preP[1] + b * 4096;
    const float* P2 = g_preP[2] + b * 4096;
    const float* P3 = g_preP[3] + b * 4096;

    for (int h = tid; h < H; h += NT) {
        float f = P0[h]        + P1[h]        + P2[h]        + P3[h]        + bias[h];
        float i = P0[1024 + h] + P1[1024 + h] + P2[1024 + h] + P3[1024 + h] + bias[1024 + h];
        float o = P0[2048 + h] + P1[2048 + h] + P2[2048 + h] + P3[2048 + h] + bias[2048 + h];
        float g = P0[3072 + h] + P1[3072 + h] + P2[3072 + h] + P3[3072 + h] + bias[3072 + h];
        float c_old = crow[h], h_old = hrow[h];
        float c1 = keep * sigf(f) * c_old + sigf(i) * tanhf(g);
        float h1 = sigf(o) * tanhf(c1);
        float hn = cp * h_old + (1.0f - cp) * h1;
        float cn = cp * c_old + (1.0f - cp) * c1;
        hn = tm * hn + (1.0f - tm) * h_old;
        cn = tm * cn + (1.0f - tm) * c_old;
        hrow[h] = hn;
        crow[h] = cn;
        spl_t(hhi, hlo, b, h, hn);
        spl_t(zhhi, zhlo, b, h, zs * hn);
        if (xnhi) spl_t(xnhi, xnlo, b, h, xnext[h]);
    }
}

__device__ void cell_l2(int b, int t, const float* bias, const int* length)
{
    const int tid = threadIdx.x;
    float* hrow = g_Ht + (2 * B + b) * H;
    float* crow = g_C  + (2 * B + b) * H;
    const float cp = 1.0f - g_Z[b];
    const float tm = (t < length[b]) ? 1.0f : 0.0f;
    const float zs = g_Z[B + b];
    const float* P0 = g_pre2P[0] + b * 4096;
    const float* P1 = g_pre2P[1] + b * 4096;
    const float* P2 = g_pre2P[2] + b * 4096;
    const float* P3 = g_pre2P[3] + b * 4096;

    for (int h = tid; h < H; h += NT) {
        float f = P0[h]        + P1[h]        + P2[h]        + P3[h]        + bias[h];
        float i = P0[1024 + h] + P1[1024 + h] + P2[1024 + h] + P3[1024 + h] + bias[1024 + h];
        float o = P0[2048 + h] + P1[2048 + h] + P2[2048 + h] + P3[2048 + h] + bias[2048 + h];
        float g = P0[3072 + h] + P1[3072 + h] + P2[3072 + h] + P3[3072 + h] + bias[3072 + h];
        float c_old = crow[h], h_old = hrow[h];
        float c1 = sigf(f) * c_old + sigf(i) * tanhf(g);
        float h1 = sigf(o) * tanhf(c1);
        float hn = cp * h_old + (1.0f - cp) * h1;
        float cn = cp * c_old + (1.0f - cp) * c1;
        hn = tm * hn + (1.0f - tm) * h_old;
        cn = tm * cn + (1.0f - tm) * c_old;
        hrow[h] = hn;
        crow[h] = cn;
        spl_t(g_Ah[4], g_Ah[5], b, h, hn);
        spl_t(g_Ah[10], g_Ah[11], b, h, zs * hn);
    }
}

__device__ void gate_row(int b, const float* Wgate, const float* bgate)
{
    const int tid = threadIdx.x;
    float s0 = 0.f, s1 = 0.f, s2 = 0.f;
    const float* hb = g_Ht + b * 3072;
    for (int j = tid; j < 3072; j += NT) {
        float h = hb[j];
        s0 += h * Wgate[j * 3 + 0];
        s1 += h * Wgate[j * 3 + 1];
        s2 += h * Wgate[j * 3 + 2];
    }
    float d0, d1, d2;
    red3(s0, s1, s2, d0, d1, d2);
    if (tid == 0) {
        g_gate[b * 3 + 0] = sigf(d0 + bgate[0]);
        g_gate[b * 3 + 1] = sigf(d1 + bgate[1]);
        g_gate[b * 3 + 2] = sigf(d2 + bgate[2]);
    }
}

// out[t,b,:] with per-segment gate scales (splits 0-3 seg0, 4-7 seg1, 8-11 seg2)
__device__ void finalize_row(int b, int t, const float* bout, float* out)
{
    const int tid = threadIdx.x;
    const float q0 = g_gate[b], q1 = g_gate[128 + b], q2 = g_gate[256 + b];
    const float gs = q0 + q1 + q2;
    float* o = out + ((size_t)t * B + b) * H;
    for (int h = tid; h < H; h += NT) {
        int i = b * H + h;
        float u0 = g_outP[0][i] + g_outP[1][i] + g_outP[2][i] + g_outP[3][i];
        float u1 = g_outP[4][i] + g_outP[5][i] + g_outP[6][i] + g_outP[7][i];
        float u2 = g_outP[8][i] + g_outP[9][i] + g_outP[10][i] + g_outP[11][i];
        o[h] = gs * bout[h] + q0 * u0 + q1 * u1 + q2 * u2;
    }
}

// ------------------------- init kernels -------------------------
// repack into tiled-swizzled hi/lo tiles: one block = one 16KB output tile
__global__ void __launch_bounds__(256)
repack_t(const float* p0, const float* p1, const float* p2, const float* p3,
         const float* p4, const float* p5, const float* p6, const float* p7,
         const float* p8)
{
    __shared__ __half sh[8192], sl[8192];
    const float* srcs[9] = {p0, p1, p2, p3, p4, p5, p6, p7, p8};
    const int slab = blockIdx.y;
    const float* src = srcs[slab];
    const int ldw = slab < 6 ? 4097 : (slab == 8 ? 1024 : 4096);
    const int ntn = (slab == 8 ? 1024 : 4096) >> 7;     // n-tiles of 128
    const int ntile = blockIdx.x >> 4, chunk = blockIdx.x & 15;
    if (ntile >= ntn) return;
    const int tid = threadIdx.x;

    for (int i = tid; i < 8192; i += 256) {
        int kk = i >> 7, r = i & 127;                    // coalesced over r
        float v = src[(size_t)(chunk * 64 + kk) * ldw + ntile * 128 + r];
        int off = r * 64 + ((((kk >> 3) & 7) ^ (r & 7)) << 3) + (kk & 7);
        __half h = __float2half_rn(v);
        sh[off] = h;
        sl[off] = __float2half_rn(v - __half2float(h));
    }
    __syncthreads();

    size_t base = (size_t)slab * SLAB + ((size_t)ntile * 16 + chunk) * 8192;
    uint4* dh = reinterpret_cast<uint4*>(g_Whi + base);
    uint4* dl = reinterpret_cast<uint4*>(g_Wlo + base);
    const uint4* xh = reinterpret_cast<const uint4*>(sh);
    const uint4* xl = reinterpret_cast<const uint4*>(sl);
    for (int i = tid; i < 1024; i += 256) { dh[i] = xh[i]; dl[i] = xl[i]; }
}

__global__ void __launch_bounds__(512)
init_misc(const float* input_,
          const float* Whh0, const float* Wbh0, const float* Wth0,
          const float* Whh1, const float* Wbh1, const float* Wth1)
{
    int idx = blockIdx.x * blockDim.x + threadIdx.x;   // 0 .. 393215
    for (int i = idx; i < 3 * B * H; i += 393216) { g_Ht[i] = 0.f; g_C[i] = 0.f; }
    for (int i = idx; i < 16 * B * H; i += 393216) g_Ah[0][i] = __ushort_as_half(0);
    if (idx < B * H) spl_t(g_Ah[12], g_Ah[13], idx >> 10, idx & 1023, input_[idx]);
    if (idx < 2 * B) g_Z[idx] = 0.f;
    if (idx < H) {
        g_zw[0][idx] = Whh0[(size_t)idx * 4097 + 4096];
        g_zw[1][idx] = Wbh0[(size_t)idx * 4097 + 4096];
        g_zw[2][idx] = Wth0[(size_t)idx * 4097 + 4096];
        g_zw[3][idx] = Whh1[(size_t)idx * 4097 + 4096];
        g_zw[4][idx] = Wbh1[(size_t)idx * 4097 + 4096];
        g_zw[5][idx] = Wth1[(size_t)idx * 4097 + 4096];
    }
    if (idx == 0) { g_count = 0; g_release = 0; }
}

// ------------------------- persistent kernel -------------------------
__global__ void __launch_bounds__(NT, 1)
hm_persist(const float* __restrict__ input_, const int* __restrict__ length,
           const float* __restrict__ b0,   const float* __restrict__ b1,
           const float* __restrict__ b2,   const float* __restrict__ bout,
           const float* __restrict__ Wgate, const float* __restrict__ bgate,
           float* __restrict__ out)
{
    extern __shared__ char smraw[];
    char* sm = (char*)(((ull)smraw + 1023) & ~1023ull);
    const unsigned smb = smem_u32(sm);

    const int tid = threadIdx.x, bx = blockIdx.x;
    if (tid == 0) {
#pragma unroll
        for (int s = 0; s < 3; s++)
            asm volatile("mbarrier.init.shared.b64 [%0], %1;"
                         :: "r"(smem_u32(&s_mb[s])), "r"(1u) : "memory");
    }
    __syncthreads();

    unsigned epoch = 0;
    int par[3] = {0, 0, 0};

    const size_t S0 = 0, S1 = SLAB, S2 = 2*(size_t)SLAB, S3 = 3*(size_t)SLAB,
                 S4 = 4*(size_t)SLAB, S5 = 5*(size_t)SLAB, S6 = 6*(size_t)SLAB,
                 S7 = 7*(size_t)SLAB, S8 = 8*(size_t)SLAB;

    const int ntB = bx >> 2, ksB = bx & 3;    // N=4096: 32 n-tiles x 4 k-splits
    const int ntO = bx & 7,  ksO = bx >> 3;   // P6: 8 n-tiles x 12 k-splits (96 CTAs)

    const float* Ht0 = g_Ht;
    const float* Ht1 = g_Ht + B * H;
    const float* Ht2 = g_Ht + 2 * B * H;
    const float bz0 = b0[4096], bz1 = b1[4096];

    for (int t = 0; t < TSTEPS; t++) {
        const float* xt = input_ + (size_t)t * B * H;
        const int xc = 12 + (t & 1) * 2;
        const int xn = 12 + ((t + 1) & 1) * 2;

        // P1: layer0 GEMM (h0@Whh0, x@Wbh0, (z0old*h1)@Wth0)
        tc_gemm(g_Ah[0], g_Ah[1], g_Ah[xc], g_Ah[xc + 1], g_Ah[8], g_Ah[9],
                S0, S1, S2, ntB * 128, ksB * 12, ksB * 12 + 12,
                g_preP[ksB], 4096, smb, par);
        if (t > 0) {
            cell_l2(bx, t - 1, b2, length);
            finalize_row(bx, t - 1, bout, out);
        }
        gsync(epoch);

        // P2: cell layer0 (z_lm1=1); writes h0 + z0new*h0; converts x[t+1]
        cell_hm(bx, 0, t, xt + bx * H, Ht1 + bx * H,
                g_zw[0], g_zw[1], g_zw[2], bz0, b0, length, 1.0f,
                g_Ah[0], g_Ah[1], g_Ah[6], g_Ah[7],
                (t + 1 < TSTEPS) ? input_ + (size_t)(t + 1) * B * H + bx * H : nullptr,
                (t + 1 < TSTEPS) ? g_Ah[xn] : nullptr, g_Ah[xn + 1]);
        gsync(epoch);

        // P3: layer1 GEMM (h1@Whh1, (z0new*h0)@Wbh1, (z1old*h2)@Wth1)
        tc_gemm(g_Ah[2], g_Ah[3], g_Ah[6], g_Ah[7], g_Ah[10], g_Ah[11],
                S3, S4, S5, ntB * 128, ksB * 12, ksB * 12 + 12,
                g_preP[ksB], 4096, smb, par);
        gsync(epoch);

        // P4: cell layer1 (z_lm1 = z0 new); writes h1 + z0*h1
        cell_hm(bx, 1, t, Ht0 + bx * H, Ht2 + bx * H,
                g_zw[3], g_zw[4], g_zw[5], bz1, b1, length, g_Z[bx],
                g_Ah[2], g_Ah[3], g_Ah[8], g_Ah[9],
                nullptr, nullptr, nullptr);
        gsync(epoch);

        // P5: layer2 GEMM (h2@Whh2, h1new@Wih2) + gate mixing
        tc_gemm(g_Ah[4], g_Ah[5], g_Ah[2], g_Ah[3], g_Ah[4], g_Ah[5],
                S6, S7, S6, ntB * 128, ksB * 8, ksB * 8 + 8,
                g_pre2P[ksB], 4096, smb, par);
        gate_row(bx, Wgate, bgate);
        gsync(epoch);

        // P6: output mix — 3 seg-aligned GEMMs on UNscaled h buffers; gate scales
        // applied in finalize. splits 0-3 -> h0 chunks 0-15, 4-7 -> h1, 8-11 -> h2.
        if (ksO < 12)
            tc_gemm(g_Ah[0], g_Ah[1], g_Ah[2], g_Ah[3], g_Ah[4], g_Ah[5],
                    S8, S8, S8, ntO * 128, ksO * 4, ksO * 4 + 4,
                    g_outP[ksO], 1024, smb, par);
        gsync(epoch);
    }

    cell_l2(bx, TSTEPS - 1, b2, length);
    finalize_row(bx, TSTEPS - 1, bout, out);
}

// ------------------------- host -------------------------
extern "C" void kernel_launch(void* const* d_in, const int* in_sizes, int n_in,
                              void* d_out, int out_size)
{
    const float* input_ = (const float*)d_in[0];
    const int*   length = (const int*)d_in[1];
    const float* Wbh0 = (const float*)d_in[2];
    const float* Whh0 = (const float*)d_in[3];
    const float* Wth0 = (const float*)d_in[4];
    const float* b0   = (const float*)d_in[5];
    const float* Wbh1 = (const float*)d_in[6];
    const float* Whh1 = (const float*)d_in[7];
    const float* Wth1 = (const float*)d_in[8];
    const float* b1   = (const float*)d_in[9];
    const float* Wih2 = (const float*)d_in[10];
    const float* Whh2 = (const float*)d_in[11];
    const float* b2   = (const float*)d_in[12];
    const float* Wout = (const float*)d_in[13];
    const float* bout = (const float*)d_in[14];
    const float* Wgate = (const float*)d_in[15];
    const float* bgate = (const float*)d_in[16];
    float* out = (float*)d_out;

    static int once = 0;
    if (!once) {
        cudaFuncSetAttribute(hm_persist, cudaFuncAttributeMaxDynamicSharedMemorySize,
                             SMEM_BYTES);
        once = 1;
    }

    // slabs: 0..5 HMLSTM (ldw 4097), 6 Whh2, 7 Wih2 (ldw 4096), 8 Wout (ldw 1024)
    repack_t<<<dim3(512, 9), 256>>>(Whh0, Wbh0, Wth0, Whh1, Wbh1, Wth1,
                                    Whh2, Wih2, Wout);
    init_misc<<<768, 512>>>(input_, Whh0, Wbh0, Wth0, Whh1, Wbh1, Wth1);
    hm_persist<<<NB, NT, SMEM_BYTES>>>(input_, length, b0, b1, b2, bout,
                                       Wgate, bgate, out);
}